// round 1
// baseline (speedup 1.0000x reference)
#include <cuda_runtime.h>
#include <math.h>

#define B_ 8
#define N_ 128
#define M_ 128
#define E_ 256
#define H_ 512

// ---------------- scratch (no allocations allowed) ----------------
__device__ float g_tn[B_ * N_ * E_];   // l2-normalized track features
__device__ float g_dn[B_ * M_ * E_];   // l2-normalized det features
__device__ float g_A [B_ * N_ * H_];   // t_n @ W1[0:E]   + b1
__device__ float g_Bv[B_ * M_ * H_];   // d_m @ W1[E:2E]

// ---------------- kernel 1: L2 normalize rows of E=256 ----------------
__global__ __launch_bounds__(256) void k_norm(const float* __restrict__ t,
                                              const float* __restrict__ d) {
    int row = blockIdx.x;
    const float* src;
    float* dst;
    if (row < B_ * N_) { src = t + row * E_;            dst = g_tn + row * E_; }
    else               { int r = row - B_ * N_;
                         src = d + r * E_;              dst = g_dn + r * E_; }
    int tid = threadIdx.x;
    float x = src[tid];
    float s = x * x;
    #pragma unroll
    for (int o = 16; o > 0; o >>= 1) s += __shfl_xor_sync(0xffffffffu, s, o);
    __shared__ float red[8];
    if ((tid & 31) == 0) red[tid >> 5] = s;
    __syncthreads();
    float tot = 0.f;
    #pragma unroll
    for (int i = 0; i < 8; i++) tot += red[i];
    float inv = 1.f / fmaxf(sqrtf(tot), 1e-12f);
    dst[tid] = x * inv;
}

// ---------------- kernel 2: A = t_n@W1a + b1 ; Bv = d_n@W1b ----------------
// grid (64, 2): y=0 -> A from g_tn, y=1 -> Bv from g_dn. 16 rows x 512 cols per block.
__global__ __launch_bounds__(256) void k_ab(const float* __restrict__ W1,
                                            const float* __restrict__ b1) {
    const int z    = blockIdx.y;
    const int row0 = blockIdx.x * 16;
    const float* X = z ? g_dn : g_tn;
    float*       O = z ? g_Bv : g_A;
    const float* W = W1 + z * (E_ * H_);   // rows [0:256) or [256:512)

    __shared__ float xs[16][17];
    __shared__ float wc[16][H_];

    const int tid = threadIdx.x, w = tid >> 5, l = tid & 31;
    float acc[2][16];
    #pragma unroll
    for (int r = 0; r < 2; r++)
        #pragma unroll
        for (int j = 0; j < 16; j++) acc[r][j] = 0.f;

    for (int c = 0; c < 16; c++) {
        __syncthreads();
        {   // x chunk: 16 rows x 16 k
            int kk = tid >> 4, r = tid & 15;
            xs[kk][r] = X[(row0 + r) * E_ + c * 16 + kk];
        }
        {   // W chunk: 16 k x 512 h, coalesced float4
            const float4* src = (const float4*)(W + c * 16 * H_);
            float4* dstp = (float4*)&wc[0][0];
            #pragma unroll
            for (int u = 0; u < 8; u++) dstp[tid + 256 * u] = src[tid + 256 * u];
        }
        __syncthreads();
        #pragma unroll 4
        for (int kk = 0; kk < 16; kk++) {
            float a0 = xs[kk][w * 2 + 0];
            float a1 = xs[kk][w * 2 + 1];
            #pragma unroll
            for (int j = 0; j < 16; j++) {
                float bv = wc[kk][l + 32 * j];
                acc[0][j] = fmaf(a0, bv, acc[0][j]);
                acc[1][j] = fmaf(a1, bv, acc[1][j]);
            }
        }
    }
    #pragma unroll
    for (int r = 0; r < 2; r++) {
        int row = row0 + w * 2 + r;
        #pragma unroll
        for (int j = 0; j < 16; j++) {
            int h = l + 32 * j;
            float v = acc[r][j] + (z == 0 ? b1[h] : 0.f);
            O[row * H_ + h] = v;
        }
    }
}

// ---------------- kernel 3: fused |t-d|@W1c GEMM + A + Bv + LN + SiLU + W2 dot ----------------
// CTA tile: 4 n x 16 m = 64 pairs, full H=512. Warp w owns pairs [8w, 8w+8),
// lane l owns h = l + 32*j (j=0..15). K=256 in 16 chunks of 16, W1c chunk
// prefetched into registers so the global load hides behind compute.
__global__ __launch_bounds__(256) void k_main(const float* __restrict__ W1,
                                              const float* __restrict__ gamma,
                                              const float* __restrict__ beta,
                                              const float* __restrict__ W2,
                                              const float* __restrict__ b2,
                                              float* __restrict__ out) {
    const int bb = blockIdx.z;
    const int n0 = blockIdx.y * 4;
    const int m0 = blockIdx.x * 16;
    const int tid = threadIdx.x, w = tid >> 5, l = tid & 31;

    __shared__ float sa[16][64];     // |t-d| chunk, k-major
    __shared__ float wc[16][H_];     // W1c chunk
    __shared__ float gam_s[H_], bet_s[H_], w2_s[H_];

    #pragma unroll
    for (int u = 0; u < 2; u++) {
        int h = tid + 256 * u;
        gam_s[h] = gamma[h];
        bet_s[h] = beta[h];
        w2_s[h]  = W2[h];
    }
    const float b2v = b2[0];

    float acc[8][16];
    #pragma unroll
    for (int p = 0; p < 8; p++)
        #pragma unroll
        for (int j = 0; j < 16; j++) acc[p][j] = 0.f;

    const float* Wc_g = W1 + (2 * E_) * H_;   // W1c rows [512:768)

    // prefetch W chunk 0 to registers
    float4 wreg[8];
    {
        const float4* src = (const float4*)Wc_g;
        #pragma unroll
        for (int u = 0; u < 8; u++) wreg[u] = src[tid + 256 * u];
    }

    // sa fill mapping: thread -> (kk, 4 consecutive pairs with same nl)
    const int kkf  = tid >> 4, q = tid & 15;
    const int nlf  = q >> 2;
    const float* trow  = g_tn + (bb * N_ + n0 + nlf) * E_;
    const float* drow0 = g_dn + (bb * M_ + m0 + (q & 3) * 4) * E_;

    for (int c = 0; c < 16; c++) {
        __syncthreads();
        {   // commit W regs -> smem
            float4* dstp = (float4*)&wc[0][0];
            #pragma unroll
            for (int u = 0; u < 8; u++) dstp[tid + 256 * u] = wreg[u];
        }
        {   // build |t-d| chunk
            int k = c * 16 + kkf;
            float tv = trow[k];
            float4 s;
            s.x = fabsf(tv - drow0[0 * E_ + k]);
            s.y = fabsf(tv - drow0[1 * E_ + k]);
            s.z = fabsf(tv - drow0[2 * E_ + k]);
            s.w = fabsf(tv - drow0[3 * E_ + k]);
            *(float4*)&sa[kkf][q * 4] = s;
        }
        __syncthreads();
        if (c < 15) {   // prefetch next W chunk; latency hidden by compute below
            const float4* src = (const float4*)(Wc_g + (c + 1) * 16 * H_);
            #pragma unroll
            for (int u = 0; u < 8; u++) wreg[u] = src[tid + 256 * u];
        }
        #pragma unroll 4
        for (int kk = 0; kk < 16; kk++) {
            float4 A0 = *(const float4*)&sa[kk][w * 8 + 0];
            float4 A1 = *(const float4*)&sa[kk][w * 8 + 4];
            float a[8] = {A0.x, A0.y, A0.z, A0.w, A1.x, A1.y, A1.z, A1.w};
            float bv[16];
            #pragma unroll
            for (int j = 0; j < 16; j++) bv[j] = wc[kk][l + 32 * j];
            #pragma unroll
            for (int p = 0; p < 8; p++)
                #pragma unroll
                for (int j = 0; j < 16; j++)
                    acc[p][j] = fmaf(a[p], bv[j], acc[p][j]);
        }
    }

    // ---- fused epilogue: + A + Bv, LayerNorm, SiLU, dot W2 ----
    const int n = n0 + (w >> 1);
    const float* Arow = g_A + (bb * N_ + n) * H_;
    #pragma unroll
    for (int p = 0; p < 8; p++) {
        const int m = m0 + (w & 1) * 8 + p;
        const float* Brow = g_Bv + (bb * M_ + m) * H_;
        float v[16];
        float s1 = 0.f;
        #pragma unroll
        for (int j = 0; j < 16; j++) {
            int h = l + 32 * j;
            v[j] = acc[p][j] + Arow[h] + Brow[h];
            s1 += v[j];
        }
        #pragma unroll
        for (int o = 16; o > 0; o >>= 1) s1 += __shfl_xor_sync(0xffffffffu, s1, o);
        float mu = s1 * (1.f / 512.f);
        float s2 = 0.f;
        #pragma unroll
        for (int j = 0; j < 16; j++) { float dd = v[j] - mu; s2 += dd * dd; }
        #pragma unroll
        for (int o = 16; o > 0; o >>= 1) s2 += __shfl_xor_sync(0xffffffffu, s2, o);
        float inv = rsqrtf(s2 * (1.f / 512.f) + 1e-5f);
        float o_ = 0.f;
        #pragma unroll
        for (int j = 0; j < 16; j++) {
            int h = l + 32 * j;
            float x = (v[j] - mu) * inv * gam_s[h] + bet_s[h];
            float sg = 1.f / (1.f + __expf(-x));
            o_ += x * sg * w2_s[h];
        }
        #pragma unroll
        for (int o = 16; o > 0; o >>= 1) o_ += __shfl_xor_sync(0xffffffffu, o_, o);
        if (l == 0) out[(bb * N_ + n) * M_ + m] = o_ + b2v;
    }
}

// ---------------- launch ----------------
extern "C" void kernel_launch(void* const* d_in, const int* in_sizes, int n_in,
                              void* d_out, int out_size) {
    const float* t     = (const float*)d_in[0];
    const float* d     = (const float*)d_in[1];
    const float* W1    = (const float*)d_in[2];
    const float* b1    = (const float*)d_in[3];
    const float* gamma = (const float*)d_in[4];
    const float* beta  = (const float*)d_in[5];
    const float* W2    = (const float*)d_in[6];
    const float* b2    = (const float*)d_in[7];
    float* out = (float*)d_out;

    k_norm<<<B_ * N_ + B_ * M_, 256>>>(t, d);
    k_ab<<<dim3(64, 2), 256>>>(W1, b1);
    dim3 g3(M_ / 16, N_ / 4, B_);
    k_main<<<g3, 256>>>(W1, gamma, beta, W2, b2, out);
}

// round 2
// speedup vs baseline: 1.0008x; 1.0008x over previous
#include <cuda_runtime.h>
#include <math.h>

#define B_ 8
#define N_ 128
#define M_ 128
#define E_ 256
#define H_ 512

// ---------------- scratch (no allocations allowed) ----------------
__device__ float g_tn[B_ * N_ * E_];   // l2-normalized track features
__device__ float g_dn[B_ * M_ * E_];   // l2-normalized det features
__device__ float g_A [B_ * N_ * H_];   // t_n @ W1[0:E]   + b1
__device__ float g_Bv[B_ * M_ * H_];   // d_m @ W1[E:2E]

// ---------------- kernel 1: L2 normalize rows of E=256 ----------------
__global__ __launch_bounds__(256) void k_norm(const float* __restrict__ t,
                                              const float* __restrict__ d) {
    int row = blockIdx.x;
    const float* src;
    float* dst;
    if (row < B_ * N_) { src = t + row * E_;            dst = g_tn + row * E_; }
    else               { int r = row - B_ * N_;
                         src = d + r * E_;              dst = g_dn + r * E_; }
    int tid = threadIdx.x;
    float x = src[tid];
    float s = x * x;
    #pragma unroll
    for (int o = 16; o > 0; o >>= 1) s += __shfl_xor_sync(0xffffffffu, s, o);
    __shared__ float red[8];
    if ((tid & 31) == 0) red[tid >> 5] = s;
    __syncthreads();
    float tot = 0.f;
    #pragma unroll
    for (int i = 0; i < 8; i++) tot += red[i];
    float inv = 1.f / fmaxf(sqrtf(tot), 1e-12f);
    dst[tid] = x * inv;
}

// ---------------- kernel 2: A = t_n@W1a + b1 ; Bv = d_n@W1b ----------------
// grid (64, 2): y=0 -> A from g_tn, y=1 -> Bv from g_dn. 16 rows x 512 cols per block.
__global__ __launch_bounds__(256) void k_ab(const float* __restrict__ W1,
                                            const float* __restrict__ b1) {
    const int z    = blockIdx.y;
    const int row0 = blockIdx.x * 16;
    const float* X = z ? g_dn : g_tn;
    float*       O = z ? g_Bv : g_A;
    const float* W = W1 + z * (E_ * H_);   // rows [0:256) or [256:512)

    __shared__ float xs[16][17];
    __shared__ float wc[16][H_];

    const int tid = threadIdx.x, w = tid >> 5, l = tid & 31;
    float acc[2][16];
    #pragma unroll
    for (int r = 0; r < 2; r++)
        #pragma unroll
        for (int j = 0; j < 16; j++) acc[r][j] = 0.f;

    for (int c = 0; c < 16; c++) {
        __syncthreads();
        {   // x chunk: 16 rows x 16 k
            int kk = tid >> 4, r = tid & 15;
            xs[kk][r] = X[(row0 + r) * E_ + c * 16 + kk];
        }
        {   // W chunk: 16 k x 512 h, coalesced float4
            const float4* src = (const float4*)(W + c * 16 * H_);
            float4* dstp = (float4*)&wc[0][0];
            #pragma unroll
            for (int u = 0; u < 8; u++) dstp[tid + 256 * u] = src[tid + 256 * u];
        }
        __syncthreads();
        #pragma unroll 4
        for (int kk = 0; kk < 16; kk++) {
            float a0 = xs[kk][w * 2 + 0];
            float a1 = xs[kk][w * 2 + 1];
            #pragma unroll
            for (int j = 0; j < 16; j++) {
                float bv = wc[kk][l + 32 * j];
                acc[0][j] = fmaf(a0, bv, acc[0][j]);
                acc[1][j] = fmaf(a1, bv, acc[1][j]);
            }
        }
    }
    #pragma unroll
    for (int r = 0; r < 2; r++) {
        int row = row0 + w * 2 + r;
        #pragma unroll
        for (int j = 0; j < 16; j++) {
            int h = l + 32 * j;
            float v = acc[r][j] + (z == 0 ? b1[h] : 0.f);
            O[row * H_ + h] = v;
        }
    }
}

// ---------------- kernel 3: fused |t-d|@W1c GEMM + A + Bv + LN + SiLU + W2 dot ----------------
// CTA tile: 4 n x 16 m = 64 pairs, full H=512. Warp w owns pairs [8w, 8w+8),
// lane l owns h = l + 32*j (j=0..15). K=256 in 16 chunks of 16, W1c chunk
// prefetched into registers so the global load hides behind compute.
__global__ __launch_bounds__(256) void k_main(const float* __restrict__ W1,
                                              const float* __restrict__ gamma,
                                              const float* __restrict__ beta,
                                              const float* __restrict__ W2,
                                              const float* __restrict__ b2,
                                              float* __restrict__ out) {
    const int bb = blockIdx.z;
    const int n0 = blockIdx.y * 4;
    const int m0 = blockIdx.x * 16;
    const int tid = threadIdx.x, w = tid >> 5, l = tid & 31;

    __shared__ float sa[16][64];     // |t-d| chunk, k-major
    __shared__ float wc[16][H_];     // W1c chunk
    __shared__ float gam_s[H_], bet_s[H_], w2_s[H_];

    #pragma unroll
    for (int u = 0; u < 2; u++) {
        int h = tid + 256 * u;
        gam_s[h] = gamma[h];
        bet_s[h] = beta[h];
        w2_s[h]  = W2[h];
    }
    const float b2v = b2[0];

    float acc[8][16];
    #pragma unroll
    for (int p = 0; p < 8; p++)
        #pragma unroll
        for (int j = 0; j < 16; j++) acc[p][j] = 0.f;

    const float* Wc_g = W1 + (2 * E_) * H_;   // W1c rows [512:768)

    // prefetch W chunk 0 to registers
    float4 wreg[8];
    {
        const float4* src = (const float4*)Wc_g;
        #pragma unroll
        for (int u = 0; u < 8; u++) wreg[u] = src[tid + 256 * u];
    }

    // sa fill mapping: thread -> (kk, 4 consecutive pairs with same nl)
    const int kkf  = tid >> 4, q = tid & 15;
    const int nlf  = q >> 2;
    const float* trow  = g_tn + (bb * N_ + n0 + nlf) * E_;
    const float* drow0 = g_dn + (bb * M_ + m0 + (q & 3) * 4) * E_;

    for (int c = 0; c < 16; c++) {
        __syncthreads();
        {   // commit W regs -> smem
            float4* dstp = (float4*)&wc[0][0];
            #pragma unroll
            for (int u = 0; u < 8; u++) dstp[tid + 256 * u] = wreg[u];
        }
        {   // build |t-d| chunk
            int k = c * 16 + kkf;
            float tv = trow[k];
            float4 s;
            s.x = fabsf(tv - drow0[0 * E_ + k]);
            s.y = fabsf(tv - drow0[1 * E_ + k]);
            s.z = fabsf(tv - drow0[2 * E_ + k]);
            s.w = fabsf(tv - drow0[3 * E_ + k]);
            *(float4*)&sa[kkf][q * 4] = s;
        }
        __syncthreads();
        if (c < 15) {   // prefetch next W chunk; latency hidden by compute below
            const float4* src = (const float4*)(Wc_g + (c + 1) * 16 * H_);
            #pragma unroll
            for (int u = 0; u < 8; u++) wreg[u] = src[tid + 256 * u];
        }
        #pragma unroll 4
        for (int kk = 0; kk < 16; kk++) {
            float4 A0 = *(const float4*)&sa[kk][w * 8 + 0];
            float4 A1 = *(const float4*)&sa[kk][w * 8 + 4];
            float a[8] = {A0.x, A0.y, A0.z, A0.w, A1.x, A1.y, A1.z, A1.w};
            float bv[16];
            #pragma unroll
            for (int j = 0; j < 16; j++) bv[j] = wc[kk][l + 32 * j];
            #pragma unroll
            for (int p = 0; p < 8; p++)
                #pragma unroll
                for (int j = 0; j < 16; j++)
                    acc[p][j] = fmaf(a[p], bv[j], acc[p][j]);
        }
    }

    // ---- fused epilogue: + A + Bv, LayerNorm, SiLU, dot W2 ----
    const int n = n0 + (w >> 1);
    const float* Arow = g_A + (bb * N_ + n) * H_;
    #pragma unroll
    for (int p = 0; p < 8; p++) {
        const int m = m0 + (w & 1) * 8 + p;
        const float* Brow = g_Bv + (bb * M_ + m) * H_;
        float v[16];
        float s1 = 0.f;
        #pragma unroll
        for (int j = 0; j < 16; j++) {
            int h = l + 32 * j;
            v[j] = acc[p][j] + Arow[h] + Brow[h];
            s1 += v[j];
        }
        #pragma unroll
        for (int o = 16; o > 0; o >>= 1) s1 += __shfl_xor_sync(0xffffffffu, s1, o);
        float mu = s1 * (1.f / 512.f);
        float s2 = 0.f;
        #pragma unroll
        for (int j = 0; j < 16; j++) { float dd = v[j] - mu; s2 += dd * dd; }
        #pragma unroll
        for (int o = 16; o > 0; o >>= 1) s2 += __shfl_xor_sync(0xffffffffu, s2, o);
        float inv = rsqrtf(s2 * (1.f / 512.f) + 1e-5f);
        float o_ = 0.f;
        #pragma unroll
        for (int j = 0; j < 16; j++) {
            int h = l + 32 * j;
            float x = (v[j] - mu) * inv * gam_s[h] + bet_s[h];
            float sg = 1.f / (1.f + __expf(-x));
            o_ += x * sg * w2_s[h];
        }
        #pragma unroll
        for (int o = 16; o > 0; o >>= 1) o_ += __shfl_xor_sync(0xffffffffu, o_, o);
        if (l == 0) out[(bb * N_ + n) * M_ + m] = o_ + b2v;
    }
}

// ---------------- launch ----------------
extern "C" void kernel_launch(void* const* d_in, const int* in_sizes, int n_in,
                              void* d_out, int out_size) {
    const float* t     = (const float*)d_in[0];
    const float* d     = (const float*)d_in[1];
    const float* W1    = (const float*)d_in[2];
    const float* b1    = (const float*)d_in[3];
    const float* gamma = (const float*)d_in[4];
    const float* beta  = (const float*)d_in[5];
    const float* W2    = (const float*)d_in[6];
    const float* b2    = (const float*)d_in[7];
    float* out = (float*)d_out;

    k_norm<<<B_ * N_ + B_ * M_, 256>>>(t, d);
    k_ab<<<dim3(64, 2), 256>>>(W1, b1);
    dim3 g3(M_ / 16, N_ / 4, B_);
    k_main<<<g3, 256>>>(W1, gamma, beta, W2, b2, out);
}

// round 5
// speedup vs baseline: 2.0612x; 2.0596x over previous
#include <cuda_runtime.h>
#include <cuda_bf16.h>
#include <stdint.h>
#include <math.h>

#define B_ 8
#define N_ 128
#define M_ 128
#define E_ 256
#define H_ 512

// ---------------- scratch (no allocations allowed) ----------------
__device__ float g_tn[B_ * N_ * E_];   // l2-normalized track features
__device__ float g_dn[B_ * M_ * E_];   // l2-normalized det features
__device__ float g_A [B_ * N_ * H_];   // t_n @ W1[0:E]   + b1
__device__ float g_Bv[B_ * M_ * H_];   // d_m @ W1[E:2E]
// W1c^T split bf16: per 32-k chunk, 512 rows (h) x [hi 64B | lo 64B], swizzled
__device__ __align__(16) unsigned char g_W[8 * 65536];

// XOR bits[4:6] of the 128B row offset with (row & 7)
#define SWZ(o) ((o) ^ (((o) >> 3) & 0x70))

__device__ __forceinline__ uint32_t smem_u32(const void* p) {
    uint32_t a;
    asm("{ .reg .u64 t; cvta.to.shared.u64 t, %1; cvt.u32.u64 %0, t; }" : "=r"(a) : "l"(p));
    return a;
}
__device__ __forceinline__ uint32_t pk2(__nv_bfloat16 a, __nv_bfloat16 b) {
    return (uint32_t)__bfloat16_as_ushort(a) | ((uint32_t)__bfloat16_as_ushort(b) << 16);
}
#define LDS32(r, a) asm volatile("ld.shared.b32 %0, [%1];" : "=r"(r) : "r"(a))
#define CP_ASYNC16(dst, src) \
    asm volatile("cp.async.cg.shared.global [%0], [%1], 16;" :: "r"(dst), "l"(src) : "memory")
#define CP_COMMIT() asm volatile("cp.async.commit_group;" ::: "memory")
#define CP_WAIT0()  asm volatile("cp.async.wait_group 0;" ::: "memory")

__device__ __forceinline__ void mma16816(float* d, const uint32_t* a,
                                         uint32_t b0, uint32_t b1) {
    asm volatile("mma.sync.aligned.m16n8k16.row.col.f32.bf16.bf16.f32 "
                 "{%0,%1,%2,%3}, {%4,%5,%6,%7}, {%8,%9}, {%0,%1,%2,%3};"
                 : "+f"(d[0]), "+f"(d[1]), "+f"(d[2]), "+f"(d[3])
                 : "r"(a[0]), "r"(a[1]), "r"(a[2]), "r"(a[3]), "r"(b0), "r"(b1));
}

// ---------------- kernel 1: L2 normalize rows of E=256 ----------------
__global__ __launch_bounds__(256) void k_norm(const float* __restrict__ t,
                                              const float* __restrict__ d) {
    int row = blockIdx.x;
    const float* src;
    float* dst;
    if (row < B_ * N_) { src = t + row * E_;            dst = g_tn + row * E_; }
    else               { int r = row - B_ * N_;
                         src = d + r * E_;              dst = g_dn + r * E_; }
    int tid = threadIdx.x;
    float x = src[tid];
    float s = x * x;
    #pragma unroll
    for (int o = 16; o > 0; o >>= 1) s += __shfl_xor_sync(0xffffffffu, s, o);
    __shared__ float red[8];
    if ((tid & 31) == 0) red[tid >> 5] = s;
    __syncthreads();
    float tot = 0.f;
    #pragma unroll
    for (int i = 0; i < 8; i++) tot += red[i];
    float inv = 1.f / fmaxf(sqrtf(tot), 1e-12f);
    dst[tid] = x * inv;
}

// ---------------- kernel 2: A = t@W1a + b1 ; Bv = d@W1b ----------------
__global__ __launch_bounds__(256) void k_ab(const float* __restrict__ W1,
                                            const float* __restrict__ b1) {
    const int z    = blockIdx.y;
    const int row0 = blockIdx.x * 16;
    const float* X = z ? g_dn : g_tn;
    float*       O = z ? g_Bv : g_A;
    const float* W = W1 + z * (E_ * H_);

    __shared__ float xs[16][17];
    __shared__ float wc[16][H_];

    const int tid = threadIdx.x, w = tid >> 5, l = tid & 31;
    float acc[2][16];
    #pragma unroll
    for (int r = 0; r < 2; r++)
        #pragma unroll
        for (int j = 0; j < 16; j++) acc[r][j] = 0.f;

    for (int c = 0; c < 16; c++) {
        __syncthreads();
        {
            int kk = tid >> 4, r = tid & 15;
            xs[kk][r] = X[(row0 + r) * E_ + c * 16 + kk];
        }
        {
            const float4* src = (const float4*)(W + c * 16 * H_);
            float4* dstp = (float4*)&wc[0][0];
            #pragma unroll
            for (int u = 0; u < 8; u++) dstp[tid + 256 * u] = src[tid + 256 * u];
        }
        __syncthreads();
        #pragma unroll 4
        for (int kk = 0; kk < 16; kk++) {
            float a0 = xs[kk][w * 2 + 0];
            float a1 = xs[kk][w * 2 + 1];
            #pragma unroll
            for (int j = 0; j < 16; j++) {
                float bv = wc[kk][l + 32 * j];
                acc[0][j] = fmaf(a0, bv, acc[0][j]);
                acc[1][j] = fmaf(a1, bv, acc[1][j]);
            }
        }
    }
    #pragma unroll
    for (int r = 0; r < 2; r++) {
        int row = row0 + w * 2 + r;
        #pragma unroll
        for (int j = 0; j < 16; j++) {
            int h = l + 32 * j;
            float v = acc[r][j] + (z == 0 ? b1[h] : 0.f);
            O[row * H_ + h] = v;
        }
    }
}

// ---------------- kernel 2b: W1c^T -> hi/lo bf16, swizzled chunk layout ----------------
// grid (8 k-chunks, 8 h-blocks of 64). Per chunk: rows h (512) x [hi 64B | lo 64B].
__global__ __launch_bounds__(256) void k_prepw(const float* __restrict__ W1) {
    __shared__ float ts_[32][65];
    const int c = blockIdx.x, hb = blockIdx.y;
    const int tid = threadIdx.x;
    {
        int kk0 = tid >> 6, hl = tid & 63;
        #pragma unroll
        for (int it = 0; it < 8; it++) {
            int k = kk0 + it * 4;
            ts_[k][hl] = W1[(2 * E_ + c * 32 + k) * H_ + hb * 64 + hl];
        }
    }
    __syncthreads();
    const int hl = tid >> 2, jj = tid & 3;
    const int h = hb * 64 + hl;
    uint32_t hi[4], lo[4];
    #pragma unroll
    for (int i = 0; i < 4; i++) {
        float x0 = ts_[jj * 8 + i * 2 + 0][hl];
        float x1 = ts_[jj * 8 + i * 2 + 1][hl];
        __nv_bfloat16 h0 = __float2bfloat16(x0), h1 = __float2bfloat16(x1);
        __nv_bfloat16 l0 = __float2bfloat16(x0 - __bfloat162float(h0));
        __nv_bfloat16 l1 = __float2bfloat16(x1 - __bfloat162float(h1));
        hi[i] = pk2(h0, h1);
        lo[i] = pk2(l0, l1);
    }
    *(uint4*)(g_W + c * 65536 + SWZ(h * 128 + jj * 16))      = make_uint4(hi[0], hi[1], hi[2], hi[3]);
    *(uint4*)(g_W + c * 65536 + SWZ(h * 128 + 64 + jj * 16)) = make_uint4(lo[0], lo[1], lo[2], lo[3]);
}

// ---------------- kernel 3: mma.sync bf16 3-pass GEMM + fused epilogue ----------------
// CTA = (b, n, m-half): 64 pairs x 512 H. 8 warps: mw = wid>>2 (32 m), hq = wid&3 (128 h).
enum {
    OFF_W    = 0,        // 2 x 64KB  W chunk double buffer
    OFF_A    = 131072,   // 2 x 8KB   |t-d| chunk double buffer
    OFF_TS   = 147456,   // 1KB  t row
    OFF_AS   = 148480,   // 2KB  A row
    OFF_GAM  = 150528,   // 2KB
    OFF_BET  = 152576,   // 2KB
    OFF_W2   = 154624,   // 2KB
    OFF_RED1 = 156672,   // 1KB  [4 hq][64 m]
    OFF_RED2 = 157696,   // 1KB
    SMEM_SZ  = 158720
};

__global__ void __launch_bounds__(256, 1) k_main(const float* __restrict__ gamma,
                                                 const float* __restrict__ beta,
                                                 const float* __restrict__ W2,
                                                 const float* __restrict__ b2,
                                                 float* __restrict__ out) {
    extern __shared__ __align__(16) char smem[];
    const uint32_t sbase = smem_u32(smem);
    const int tid = threadIdx.x, wid = tid >> 5, lid = tid & 31;
    const int b = blockIdx.z, n = blockIdx.y, m0 = blockIdx.x * 64;
    const int mw = wid >> 2, hq = wid & 3;

    float* ts   = (float*)(smem + OFF_TS);
    float* as_  = (float*)(smem + OFF_AS);
    float* gam  = (float*)(smem + OFF_GAM);
    float* bet  = (float*)(smem + OFF_BET);
    float* w2s  = (float*)(smem + OFF_W2);
    float* red1 = (float*)(smem + OFF_RED1);
    float* red2 = (float*)(smem + OFF_RED2);

    ts[tid] = g_tn[(b * N_ + n) * E_ + tid];
    #pragma unroll
    for (int u = 0; u < 2; u++) {
        int h = tid + 256 * u;
        as_[h] = g_A[(b * N_ + n) * H_ + h];
        gam[h] = gamma[h];
        bet[h] = beta[h];
        w2s[h] = W2[h];
    }
    __syncthreads();   // <<< FIX: ts[] must be fully written before buildA reads it

    // ---- chunk loaders ----
    const int am = tid >> 2, aj = tid & 3;   // A-build mapping: m row, 8-k slice
    const float* drowA = g_dn + (b * M_ + m0 + am) * E_;

    auto buildA = [&](int c, int buf) {
        const float* dp = drowA + c * 32 + aj * 8;
        float4 d0 = *(const float4*)dp;
        float4 d1 = *(const float4*)(dp + 4);
        const float* tp = ts + c * 32 + aj * 8;
        float x[8];
        x[0] = fabsf(tp[0] - d0.x); x[1] = fabsf(tp[1] - d0.y);
        x[2] = fabsf(tp[2] - d0.z); x[3] = fabsf(tp[3] - d0.w);
        x[4] = fabsf(tp[4] - d1.x); x[5] = fabsf(tp[5] - d1.y);
        x[6] = fabsf(tp[6] - d1.z); x[7] = fabsf(tp[7] - d1.w);
        uint32_t hi[4], lo[4];
        #pragma unroll
        for (int i = 0; i < 4; i++) {
            __nv_bfloat16 h0 = __float2bfloat16(x[2 * i + 0]);
            __nv_bfloat16 h1 = __float2bfloat16(x[2 * i + 1]);
            __nv_bfloat16 l0 = __float2bfloat16(x[2 * i + 0] - __bfloat162float(h0));
            __nv_bfloat16 l1 = __float2bfloat16(x[2 * i + 1] - __bfloat162float(h1));
            hi[i] = pk2(h0, h1);
            lo[i] = pk2(l0, l1);
        }
        char* abuf = smem + OFF_A + buf * 8192;
        *(uint4*)(abuf + SWZ(am * 128 + aj * 16))      = make_uint4(hi[0], hi[1], hi[2], hi[3]);
        *(uint4*)(abuf + SWZ(am * 128 + 64 + aj * 16)) = make_uint4(lo[0], lo[1], lo[2], lo[3]);
    };
    auto loadW = [&](int c, int buf) {
        const char* src = (const char*)g_W + c * 65536 + tid * 16;
        uint32_t dst = sbase + OFF_W + buf * 65536 + tid * 16;
        #pragma unroll
        for (int u = 0; u < 16; u++)
            CP_ASYNC16(dst + u * 4096, src + u * 4096);
    };

    // ---- accumulators + fragment addressing ----
    float acc[2][16][4];
    #pragma unroll
    for (int mt = 0; mt < 2; mt++)
        #pragma unroll
        for (int nt = 0; nt < 16; nt++)
            #pragma unroll
            for (int r = 0; r < 4; r++) acc[mt][nt][r] = 0.f;

    const uint32_t xorv = (uint32_t)(lid >> 2) << 4;
    const uint32_t j4   = (uint32_t)(lid & 3) << 2;

    auto gemm = [&](int buf) {
        const uint32_t aBase = sbase + OFF_A + buf * 8192  + (mw * 32 + (lid >> 2)) * 128;
        const uint32_t bBase = sbase + OFF_W + buf * 65536 + (hq * 128 + (lid >> 2)) * 128;
        #pragma unroll
        for (int pass = 0; pass < 3; pass++) {
            const uint32_t ah = (pass == 2) ? 64u : 0u;
            const uint32_t bh = (pass == 1) ? 64u : 0u;
            #pragma unroll
            for (int ks = 0; ks < 2; ks++) {
                const uint32_t ka0 = ((ah + ks * 32)      ^ xorv) + j4;
                const uint32_t ka1 = ((ah + ks * 32 + 16) ^ xorv) + j4;
                const uint32_t kb0 = ((bh + ks * 32)      ^ xorv) + j4;
                const uint32_t kb1 = ((bh + ks * 32 + 16) ^ xorv) + j4;
                uint32_t af[2][4];
                #pragma unroll
                for (int mt = 0; mt < 2; mt++) {
                    uint32_t r0 = aBase + mt * 2048;
                    LDS32(af[mt][0], r0 + ka0);
                    LDS32(af[mt][1], r0 + 1024 + ka0);
                    LDS32(af[mt][2], r0 + ka1);
                    LDS32(af[mt][3], r0 + 1024 + ka1);
                }
                #pragma unroll
                for (int nt = 0; nt < 16; nt++) {
                    uint32_t bb = bBase + nt * 1024;
                    uint32_t b0, b1;
                    LDS32(b0, bb + kb0);
                    LDS32(b1, bb + kb1);
                    mma16816(acc[0][nt], af[0], b0, b1);
                    mma16816(acc[1][nt], af[1], b0, b1);
                }
            }
        }
    };

    // ---- pipelined K loop (8 chunks of 32) ----
    buildA(0, 0);
    loadW(0, 0);
    CP_COMMIT();
    CP_WAIT0();
    __syncthreads();
    for (int c = 0; c < 8; c++) {
        const int buf = c & 1;
        if (c < 7) {
            loadW(c + 1, buf ^ 1);
            CP_COMMIT();
            buildA(c + 1, buf ^ 1);
        }
        gemm(buf);
        if (c < 7) CP_WAIT0();
        __syncthreads();
    }

    // ---- fused epilogue ----
    const float b2v = b2[0];
    float s1[2][2] = {{0.f, 0.f}, {0.f, 0.f}};
    float s2[2][2] = {{0.f, 0.f}, {0.f, 0.f}};
    const int mbase = m0 + mw * 32;
    #pragma unroll
    for (int mt = 0; mt < 2; mt++) {
        #pragma unroll
        for (int half = 0; half < 2; half++) {
            const int mr = mt * 16 + (lid >> 2) + half * 8;
            const float* bp = g_Bv + (b * M_ + mbase + mr) * H_ + hq * 128 + (lid & 3) * 2;
            #pragma unroll
            for (int nt = 0; nt < 16; nt++) {
                float2 bv = *(const float2*)(bp + nt * 8);
                int h = hq * 128 + nt * 8 + (lid & 3) * 2;
                float v0 = acc[mt][nt][half * 2 + 0] + as_[h + 0] + bv.x;
                float v1 = acc[mt][nt][half * 2 + 1] + as_[h + 1] + bv.y;
                acc[mt][nt][half * 2 + 0] = v0;
                acc[mt][nt][half * 2 + 1] = v1;
                s1[mt][half] += v0 + v1;
                s2[mt][half] = fmaf(v0, v0, fmaf(v1, v1, s2[mt][half]));
            }
        }
    }
    #pragma unroll
    for (int mt = 0; mt < 2; mt++)
        #pragma unroll
        for (int half = 0; half < 2; half++)
            #pragma unroll
            for (int o = 1; o <= 2; o <<= 1) {
                s1[mt][half] += __shfl_xor_sync(0xffffffffu, s1[mt][half], o);
                s2[mt][half] += __shfl_xor_sync(0xffffffffu, s2[mt][half], o);
            }
    if ((lid & 3) == 0) {
        #pragma unroll
        for (int mt = 0; mt < 2; mt++)
            #pragma unroll
            for (int half = 0; half < 2; half++) {
                int m = mw * 32 + mt * 16 + (lid >> 2) + half * 8;
                red1[hq * 64 + m] = s1[mt][half];
                red2[hq * 64 + m] = s2[mt][half];
            }
    }
    __syncthreads();
    float mu[2][2], inv[2][2];
    #pragma unroll
    for (int mt = 0; mt < 2; mt++)
        #pragma unroll
        for (int half = 0; half < 2; half++) {
            int m = mw * 32 + mt * 16 + (lid >> 2) + half * 8;
            float S1 = red1[m] + red1[64 + m] + red1[128 + m] + red1[192 + m];
            float S2 = red2[m] + red2[64 + m] + red2[128 + m] + red2[192 + m];
            float mm = S1 * (1.f / 512.f);
            mu[mt][half]  = mm;
            inv[mt][half] = rsqrtf(fmaxf(S2 * (1.f / 512.f) - mm * mm, 0.f) + 1e-5f);
        }
    __syncthreads();   // red buffers reused below

    float o_[2][2] = {{0.f, 0.f}, {0.f, 0.f}};
    #pragma unroll
    for (int mt = 0; mt < 2; mt++) {
        #pragma unroll
        for (int half = 0; half < 2; half++) {
            float mm = mu[mt][half], iv = inv[mt][half];
            #pragma unroll
            for (int nt = 0; nt < 16; nt++) {
                int h = hq * 128 + nt * 8 + (lid & 3) * 2;
                #pragma unroll
                for (int e = 0; e < 2; e++) {
                    float v = acc[mt][nt][half * 2 + e];
                    float x = fmaf((v - mm) * iv, gam[h + e], bet[h + e]);
                    float sg = 1.f / (1.f + __expf(-x));
                    o_[mt][half] = fmaf(x * sg, w2s[h + e], o_[mt][half]);
                }
            }
        }
    }
    #pragma unroll
    for (int mt = 0; mt < 2; mt++)
        #pragma unroll
        for (int half = 0; half < 2; half++)
            #pragma unroll
            for (int o = 1; o <= 2; o <<= 1)
                o_[mt][half] += __shfl_xor_sync(0xffffffffu, o_[mt][half], o);
    if ((lid & 3) == 0) {
        #pragma unroll
        for (int mt = 0; mt < 2; mt++)
            #pragma unroll
            for (int half = 0; half < 2; half++) {
                int m = mw * 32 + mt * 16 + (lid >> 2) + half * 8;
                red1[hq * 64 + m] = o_[mt][half];
            }
    }
    __syncthreads();
    if (tid < 64) {
        int m = tid;
        float oo = red1[m] + red1[64 + m] + red1[128 + m] + red1[192 + m] + b2v;
        out[(b * N_ + n) * M_ + m0 + m] = oo;
    }
}

// ---------------- launch ----------------
extern "C" void kernel_launch(void* const* d_in, const int* in_sizes, int n_in,
                              void* d_out, int out_size) {
    const float* t     = (const float*)d_in[0];
    const float* d     = (const float*)d_in[1];
    const float* W1    = (const float*)d_in[2];
    const float* b1    = (const float*)d_in[3];
    const float* gamma = (const float*)d_in[4];
    const float* beta  = (const float*)d_in[5];
    const float* W2    = (const float*)d_in[6];
    const float* b2    = (const float*)d_in[7];
    float* out = (float*)d_out;

    cudaFuncSetAttribute(k_main, cudaFuncAttributeMaxDynamicSharedMemorySize, SMEM_SZ);

    k_norm<<<B_ * N_ + B_ * M_, 256>>>(t, d);
    k_prepw<<<dim3(8, 8), 256>>>(W1);
    k_ab<<<dim3(64, 2), 256>>>(W1, b1);
    k_main<<<dim3(2, N_, B_), 256, SMEM_SZ>>>(gamma, beta, W2, b2, out);
}

// round 6
// speedup vs baseline: 2.2380x; 1.0858x over previous
#include <cuda_runtime.h>
#include <cuda_bf16.h>
#include <stdint.h>
#include <math.h>

#define B_ 8
#define N_ 128
#define M_ 128
#define E_ 256
#define H_ 512

// ---------------- scratch (no allocations allowed) ----------------
__device__ float g_tn[B_ * N_ * E_];   // l2-normalized track features
__device__ float g_dn[B_ * M_ * E_];   // l2-normalized det features
__device__ float g_A [B_ * N_ * H_];   // t_n @ W1[0:E]   + b1
__device__ float g_Bv[B_ * M_ * H_];   // d_m @ W1[E:2E]
// W1c^T split bf16: per 32-k chunk, 512 rows (h) x [hi 64B | lo 64B], swizzled
__device__ __align__(16) unsigned char g_W[8 * 65536];

// XOR bits[4:6] of the 128B row offset with (row & 7)
#define SWZ(o) ((o) ^ (((o) >> 3) & 0x70))

__device__ __forceinline__ uint32_t smem_u32(const void* p) {
    uint32_t a;
    asm("{ .reg .u64 t; cvta.to.shared.u64 t, %1; cvt.u32.u64 %0, t; }" : "=r"(a) : "l"(p));
    return a;
}
__device__ __forceinline__ uint32_t pk2(__nv_bfloat16 a, __nv_bfloat16 b) {
    return (uint32_t)__bfloat16_as_ushort(a) | ((uint32_t)__bfloat16_as_ushort(b) << 16);
}
#define CP_ASYNC16(dst, src) \
    asm volatile("cp.async.cg.shared.global [%0], [%1], 16;" :: "r"(dst), "l"(src) : "memory")
#define CP_COMMIT() asm volatile("cp.async.commit_group;" ::: "memory")
#define CP_WAIT0()  asm volatile("cp.async.wait_group 0;" ::: "memory")

#define LDMX4(r0, r1, r2, r3, addr) \
    asm volatile("ldmatrix.sync.aligned.m8n8.x4.shared.b16 {%0,%1,%2,%3}, [%4];" \
                 : "=r"(r0), "=r"(r1), "=r"(r2), "=r"(r3) : "r"(addr))

__device__ __forceinline__ void mma16816(float* d, const uint32_t* a,
                                         uint32_t b0, uint32_t b1) {
    asm volatile("mma.sync.aligned.m16n8k16.row.col.f32.bf16.bf16.f32 "
                 "{%0,%1,%2,%3}, {%4,%5,%6,%7}, {%8,%9}, {%0,%1,%2,%3};"
                 : "+f"(d[0]), "+f"(d[1]), "+f"(d[2]), "+f"(d[3])
                 : "r"(a[0]), "r"(a[1]), "r"(a[2]), "r"(a[3]), "r"(b0), "r"(b1));
}

// ---------------- kernel 1: L2 normalize rows of E=256 ----------------
__global__ __launch_bounds__(256) void k_norm(const float* __restrict__ t,
                                              const float* __restrict__ d) {
    int row = blockIdx.x;
    const float* src;
    float* dst;
    if (row < B_ * N_) { src = t + row * E_;            dst = g_tn + row * E_; }
    else               { int r = row - B_ * N_;
                         src = d + r * E_;              dst = g_dn + r * E_; }
    int tid = threadIdx.x;
    float x = src[tid];
    float s = x * x;
    #pragma unroll
    for (int o = 16; o > 0; o >>= 1) s += __shfl_xor_sync(0xffffffffu, s, o);
    __shared__ float red[8];
    if ((tid & 31) == 0) red[tid >> 5] = s;
    __syncthreads();
    float tot = 0.f;
    #pragma unroll
    for (int i = 0; i < 8; i++) tot += red[i];
    float inv = 1.f / fmaxf(sqrtf(tot), 1e-12f);
    dst[tid] = x * inv;
}

// ---------------- kernel 2: A = t@W1a + b1 ; Bv = d@W1b ----------------
__global__ __launch_bounds__(256) void k_ab(const float* __restrict__ W1,
                                            const float* __restrict__ b1) {
    const int z    = blockIdx.y;
    const int row0 = blockIdx.x * 16;
    const float* X = z ? g_dn : g_tn;
    float*       O = z ? g_Bv : g_A;
    const float* W = W1 + z * (E_ * H_);

    __shared__ float xs[16][17];
    __shared__ float wc[16][H_];

    const int tid = threadIdx.x, w = tid >> 5, l = tid & 31;
    float acc[2][16];
    #pragma unroll
    for (int r = 0; r < 2; r++)
        #pragma unroll
        for (int j = 0; j < 16; j++) acc[r][j] = 0.f;

    for (int c = 0; c < 16; c++) {
        __syncthreads();
        {
            int kk = tid >> 4, r = tid & 15;
            xs[kk][r] = X[(row0 + r) * E_ + c * 16 + kk];
        }
        {
            const float4* src = (const float4*)(W + c * 16 * H_);
            float4* dstp = (float4*)&wc[0][0];
            #pragma unroll
            for (int u = 0; u < 8; u++) dstp[tid + 256 * u] = src[tid + 256 * u];
        }
        __syncthreads();
        #pragma unroll 4
        for (int kk = 0; kk < 16; kk++) {
            float a0 = xs[kk][w * 2 + 0];
            float a1 = xs[kk][w * 2 + 1];
            #pragma unroll
            for (int j = 0; j < 16; j++) {
                float bv = wc[kk][l + 32 * j];
                acc[0][j] = fmaf(a0, bv, acc[0][j]);
                acc[1][j] = fmaf(a1, bv, acc[1][j]);
            }
        }
    }
    #pragma unroll
    for (int r = 0; r < 2; r++) {
        int row = row0 + w * 2 + r;
        #pragma unroll
        for (int j = 0; j < 16; j++) {
            int h = l + 32 * j;
            float v = acc[r][j] + (z == 0 ? b1[h] : 0.f);
            O[row * H_ + h] = v;
        }
    }
}

// ---------------- kernel 2b: W1c^T -> hi/lo bf16, swizzled chunk layout ----------------
__global__ __launch_bounds__(256) void k_prepw(const float* __restrict__ W1) {
    __shared__ float ts_[32][65];
    const int c = blockIdx.x, hb = blockIdx.y;
    const int tid = threadIdx.x;
    {
        int kk0 = tid >> 6, hl = tid & 63;
        #pragma unroll
        for (int it = 0; it < 8; it++) {
            int k = kk0 + it * 4;
            ts_[k][hl] = W1[(2 * E_ + c * 32 + k) * H_ + hb * 64 + hl];
        }
    }
    __syncthreads();
    const int hl = tid >> 2, jj = tid & 3;
    const int h = hb * 64 + hl;
    uint32_t hi[4], lo[4];
    #pragma unroll
    for (int i = 0; i < 4; i++) {
        float x0 = ts_[jj * 8 + i * 2 + 0][hl];
        float x1 = ts_[jj * 8 + i * 2 + 1][hl];
        __nv_bfloat16 h0 = __float2bfloat16(x0), h1 = __float2bfloat16(x1);
        __nv_bfloat16 l0 = __float2bfloat16(x0 - __bfloat162float(h0));
        __nv_bfloat16 l1 = __float2bfloat16(x1 - __bfloat162float(h1));
        hi[i] = pk2(h0, h1);
        lo[i] = pk2(l0, l1);
    }
    *(uint4*)(g_W + c * 65536 + SWZ(h * 128 + jj * 16))      = make_uint4(hi[0], hi[1], hi[2], hi[3]);
    *(uint4*)(g_W + c * 65536 + SWZ(h * 128 + 64 + jj * 16)) = make_uint4(lo[0], lo[1], lo[2], lo[3]);
}

// ---------------- kernel 3: mma.sync bf16 3-pass GEMM + fused epilogue ----------------
// CTA = (b, n, m-half): 64 pairs x 512 H, 512 threads / 16 warps.
// Warp tile: mw = wid>>3 (32 m), hq = wid&7 (64 h). ldmatrix.x4 fragment loads.
enum {
    OFF_W    = 0,        // 2 x 64KB  W chunk double buffer
    OFF_A    = 131072,   // 2 x 8KB   |t-d| chunk double buffer
    OFF_TS   = 147456,   // 1KB  t row
    OFF_AS   = 148480,   // 2KB  A row
    OFF_GAM  = 150528,   // 2KB
    OFF_BET  = 152576,   // 2KB
    OFF_W2   = 154624,   // 2KB
    OFF_RED1 = 156672,   // 2KB  [8 hq][64 m]
    OFF_RED2 = 158720,   // 2KB
    SMEM_SZ  = 160768
};

__global__ void __launch_bounds__(512, 1) k_main(const float* __restrict__ gamma,
                                                 const float* __restrict__ beta,
                                                 const float* __restrict__ W2,
                                                 const float* __restrict__ b2,
                                                 float* __restrict__ out) {
    extern __shared__ __align__(16) char smem[];
    const uint32_t sbase = smem_u32(smem);
    const int tid = threadIdx.x, wid = tid >> 5, lid = tid & 31;
    const int b = blockIdx.z, n = blockIdx.y, m0 = blockIdx.x * 64;
    const int mw = wid >> 3, hq = wid & 7;

    float* ts   = (float*)(smem + OFF_TS);
    float* as_  = (float*)(smem + OFF_AS);
    float* gam  = (float*)(smem + OFF_GAM);
    float* bet  = (float*)(smem + OFF_BET);
    float* w2s  = (float*)(smem + OFF_W2);
    float* red1 = (float*)(smem + OFF_RED1);
    float* red2 = (float*)(smem + OFF_RED2);

    if (tid < 256) ts[tid] = g_tn[(b * N_ + n) * E_ + tid];
    {
        int h = tid;
        as_[h] = g_A[(b * N_ + n) * H_ + h];
        gam[h] = gamma[h];
        bet[h] = beta[h];
        w2s[h] = W2[h];
    }
    __syncthreads();

    // ---- chunk loaders ----
    const int am = tid >> 3, aj = tid & 7;   // A-build: m row (64), 4-k slice (8)
    const float* drowA = g_dn + (b * M_ + m0 + am) * E_;

    auto buildA = [&](int c, int buf) {
        const float4 dv = *(const float4*)(drowA + c * 32 + aj * 4);
        const float* tp = ts + c * 32 + aj * 4;
        float x0 = fabsf(tp[0] - dv.x), x1 = fabsf(tp[1] - dv.y);
        float x2 = fabsf(tp[2] - dv.z), x3 = fabsf(tp[3] - dv.w);
        __nv_bfloat16 h0 = __float2bfloat16(x0), h1 = __float2bfloat16(x1);
        __nv_bfloat16 h2 = __float2bfloat16(x2), h3 = __float2bfloat16(x3);
        __nv_bfloat16 l0 = __float2bfloat16(x0 - __bfloat162float(h0));
        __nv_bfloat16 l1 = __float2bfloat16(x1 - __bfloat162float(h1));
        __nv_bfloat16 l2 = __float2bfloat16(x2 - __bfloat162float(h2));
        __nv_bfloat16 l3 = __float2bfloat16(x3 - __bfloat162float(h3));
        char* abuf = smem + OFF_A + buf * 8192;
        *(uint2*)(abuf + SWZ(am * 128 + aj * 8))      = make_uint2(pk2(h0, h1), pk2(h2, h3));
        *(uint2*)(abuf + SWZ(am * 128 + 64 + aj * 8)) = make_uint2(pk2(l0, l1), pk2(l2, l3));
    };
    auto loadW = [&](int c, int buf) {
        const char* src = (const char*)g_W + c * 65536 + tid * 16;
        uint32_t dst = sbase + OFF_W + buf * 65536 + tid * 16;
        #pragma unroll
        for (int u = 0; u < 8; u++)
            CP_ASYNC16(dst + u * 8192, src + u * 8192);
    };

    // ---- accumulators + ldmatrix addressing ----
    float acc[2][8][4];
    #pragma unroll
    for (int mt = 0; mt < 2; mt++)
        #pragma unroll
        for (int nt = 0; nt < 8; nt++)
            #pragma unroll
            for (int r = 0; r < 4; r++) acc[mt][nt][r] = 0.f;

    // A: lanes 0-7 (m0-7,klo), 8-15 (m8-15,klo), 16-23 (m0-7,khi), 24-31 (m8-15,khi)
    const uint32_t arowoff = (uint32_t)(mw * 32 + (lid & 15)) * 128;
    const uint32_t asel    = (uint32_t)(lid >> 4) * 16;
    // B: lanes 0-7 (n0-7,klo), 8-15 (n0-7,khi), 16-23 (n8-15,klo), 24-31 (n8-15,khi)
    const uint32_t browoff = (uint32_t)(hq * 64 + (lid & 7) + ((lid >> 4) << 3)) * 128;
    const uint32_t bsel    = (uint32_t)((lid >> 3) & 1) * 16;
    const uint32_t xr      = (uint32_t)(lid & 7) << 4;

    auto gemm = [&](int buf) {
        const uint32_t aBase = sbase + OFF_A + buf * 8192  + arowoff;
        const uint32_t bBase = sbase + OFF_W + buf * 65536 + browoff;
        #pragma unroll
        for (int pass = 0; pass < 3; pass++) {
            const uint32_t ah = (pass == 2) ? 64u : 0u;
            const uint32_t bh = (pass == 1) ? 64u : 0u;
            #pragma unroll
            for (int ks = 0; ks < 2; ks++) {
                const uint32_t aoff = (ah + ks * 32 + asel) ^ xr;
                const uint32_t boff = (bh + ks * 32 + bsel) ^ xr;
                uint32_t af[2][4];
                #pragma unroll
                for (int mt = 0; mt < 2; mt++)
                    LDMX4(af[mt][0], af[mt][1], af[mt][2], af[mt][3],
                          aBase + mt * 2048 + aoff);
                uint32_t bf[4][4];
                #pragma unroll
                for (int np = 0; np < 4; np++)
                    LDMX4(bf[np][0], bf[np][1], bf[np][2], bf[np][3],
                          bBase + np * 2048 + boff);
                #pragma unroll
                for (int np = 0; np < 4; np++) {
                    mma16816(acc[0][2 * np + 0], af[0], bf[np][0], bf[np][1]);
                    mma16816(acc[1][2 * np + 0], af[1], bf[np][0], bf[np][1]);
                    mma16816(acc[0][2 * np + 1], af[0], bf[np][2], bf[np][3]);
                    mma16816(acc[1][2 * np + 1], af[1], bf[np][2], bf[np][3]);
                }
            }
        }
    };

    // ---- pipelined K loop (8 chunks of 32) ----
    buildA(0, 0);
    loadW(0, 0);
    CP_COMMIT();
    CP_WAIT0();
    __syncthreads();
    for (int c = 0; c < 8; c++) {
        const int buf = c & 1;
        if (c < 7) {
            loadW(c + 1, buf ^ 1);
            CP_COMMIT();
            buildA(c + 1, buf ^ 1);
        }
        gemm(buf);
        if (c < 7) CP_WAIT0();
        __syncthreads();
    }

    // ---- fused epilogue ----
    const float b2v = b2[0];
    float s1[2][2] = {{0.f, 0.f}, {0.f, 0.f}};
    float s2[2][2] = {{0.f, 0.f}, {0.f, 0.f}};
    const int mbase = m0 + mw * 32;
    #pragma unroll
    for (int mt = 0; mt < 2; mt++) {
        #pragma unroll
        for (int half = 0; half < 2; half++) {
            const int mr = mt * 16 + (lid >> 2) + half * 8;
            const float* bp = g_Bv + (b * M_ + mbase + mr) * H_ + hq * 64 + (lid & 3) * 2;
            #pragma unroll
            for (int nt = 0; nt < 8; nt++) {
                float2 bv = *(const float2*)(bp + nt * 8);
                int h = hq * 64 + nt * 8 + (lid & 3) * 2;
                float v0 = acc[mt][nt][half * 2 + 0] + as_[h + 0] + bv.x;
                float v1 = acc[mt][nt][half * 2 + 1] + as_[h + 1] + bv.y;
                acc[mt][nt][half * 2 + 0] = v0;
                acc[mt][nt][half * 2 + 1] = v1;
                s1[mt][half] += v0 + v1;
                s2[mt][half] = fmaf(v0, v0, fmaf(v1, v1, s2[mt][half]));
            }
        }
    }
    #pragma unroll
    for (int mt = 0; mt < 2; mt++)
        #pragma unroll
        for (int half = 0; half < 2; half++)
            #pragma unroll
            for (int o = 1; o <= 2; o <<= 1) {
                s1[mt][half] += __shfl_xor_sync(0xffffffffu, s1[mt][half], o);
                s2[mt][half] += __shfl_xor_sync(0xffffffffu, s2[mt][half], o);
            }
    if ((lid & 3) == 0) {
        #pragma unroll
        for (int mt = 0; mt < 2; mt++)
            #pragma unroll
            for (int half = 0; half < 2; half++) {
                int m = mw * 32 + mt * 16 + (lid >> 2) + half * 8;
                red1[hq * 64 + m] = s1[mt][half];
                red2[hq * 64 + m] = s2[mt][half];
            }
    }
    __syncthreads();
    float mu[2][2], inv[2][2];
    #pragma unroll
    for (int mt = 0; mt < 2; mt++)
        #pragma unroll
        for (int half = 0; half < 2; half++) {
            int m = mw * 32 + mt * 16 + (lid >> 2) + half * 8;
            float S1 = 0.f, S2 = 0.f;
            #pragma unroll
            for (int q = 0; q < 8; q++) {
                S1 += red1[q * 64 + m];
                S2 += red2[q * 64 + m];
            }
            float mm = S1 * (1.f / 512.f);
            mu[mt][half]  = mm;
            inv[mt][half] = rsqrtf(fmaxf(S2 * (1.f / 512.f) - mm * mm, 0.f) + 1e-5f);
        }
    __syncthreads();   // red buffers reused below

    float o_[2][2] = {{0.f, 0.f}, {0.f, 0.f}};
    #pragma unroll
    for (int mt = 0; mt < 2; mt++) {
        #pragma unroll
        for (int half = 0; half < 2; half++) {
            float mm = mu[mt][half], iv = inv[mt][half];
            #pragma unroll
            for (int nt = 0; nt < 8; nt++) {
                int h = hq * 64 + nt * 8 + (lid & 3) * 2;
                #pragma unroll
                for (int e = 0; e < 2; e++) {
                    float v = acc[mt][nt][half * 2 + e];
                    float x = fmaf((v - mm) * iv, gam[h + e], bet[h + e]);
                    float sg = 1.f / (1.f + __expf(-x));
                    o_[mt][half] = fmaf(x * sg, w2s[h + e], o_[mt][half]);
                }
            }
        }
    }
    #pragma unroll
    for (int mt = 0; mt < 2; mt++)
        #pragma unroll
        for (int half = 0; half < 2; half++)
            #pragma unroll
            for (int o = 1; o <= 2; o <<= 1)
                o_[mt][half] += __shfl_xor_sync(0xffffffffu, o_[mt][half], o);
    if ((lid & 3) == 0) {
        #pragma unroll
        for (int mt = 0; mt < 2; mt++)
            #pragma unroll
            for (int half = 0; half < 2; half++) {
                int m = mw * 32 + mt * 16 + (lid >> 2) + half * 8;
                red1[hq * 64 + m] = o_[mt][half];
            }
    }
    __syncthreads();
    if (tid < 64) {
        int m = tid;
        float oo = b2v;
        #pragma unroll
        for (int q = 0; q < 8; q++) oo += red1[q * 64 + m];
        out[(b * N_ + n) * M_ + m0 + m] = oo;
    }
}

// ---------------- launch ----------------
extern "C" void kernel_launch(void* const* d_in, const int* in_sizes, int n_in,
                              void* d_out, int out_size) {
    const float* t     = (const float*)d_in[0];
    const float* d     = (const float*)d_in[1];
    const float* W1    = (const float*)d_in[2];
    const float* b1    = (const float*)d_in[3];
    const float* gamma = (const float*)d_in[4];
    const float* beta  = (const float*)d_in[5];
    const float* W2    = (const float*)d_in[6];
    const float* b2    = (const float*)d_in[7];
    float* out = (float*)d_out;

    cudaFuncSetAttribute(k_main, cudaFuncAttributeMaxDynamicSharedMemorySize, SMEM_SZ);

    k_norm<<<B_ * N_ + B_ * M_, 256>>>(t, d);
    k_prepw<<<dim3(8, 8), 256>>>(W1);
    k_ab<<<dim3(64, 2), 256>>>(W1, b1);
    k_main<<<dim3(2, N_, B_), 512, SMEM_SZ>>>(gamma, beta, W2, b2, out);
}

// round 7
// speedup vs baseline: 2.3894x; 1.0676x over previous
#include <cuda_runtime.h>
#include <cuda_bf16.h>
#include <stdint.h>
#include <math.h>

#define B_ 8
#define N_ 128
#define M_ 128
#define E_ 256
#define H_ 512

// ---------------- scratch (no allocations allowed) ----------------
__device__ float g_tn[B_ * N_ * E_];   // l2-normalized track features
__device__ float g_dn[B_ * M_ * E_];   // l2-normalized det features
__device__ float g_A [B_ * N_ * H_];   // t_n @ W1[0:E]   + b1
__device__ float g_Bv[B_ * M_ * H_];   // d_m @ W1[E:2E]
// W1c^T split bf16: per 32-k chunk, 512 rows (h) x [hi 64B | lo 64B], swizzled
__device__ __align__(16) unsigned char g_W[8 * 65536];

// XOR bits[4:6] of the 128B row offset with (row & 7)
#define SWZ(o) ((o) ^ (((o) >> 3) & 0x70))

__device__ __forceinline__ uint32_t smem_u32(const void* p) {
    uint32_t a;
    asm("{ .reg .u64 t; cvta.to.shared.u64 t, %1; cvt.u32.u64 %0, t; }" : "=r"(a) : "l"(p));
    return a;
}
__device__ __forceinline__ uint32_t pk2(__nv_bfloat16 a, __nv_bfloat16 b) {
    return (uint32_t)__bfloat16_as_ushort(a) | ((uint32_t)__bfloat16_as_ushort(b) << 16);
}
#define CP_ASYNC16(dst, src) \
    asm volatile("cp.async.cg.shared.global [%0], [%1], 16;" :: "r"(dst), "l"(src) : "memory")
#define CP_COMMIT() asm volatile("cp.async.commit_group;" ::: "memory")
#define CP_WAIT0()  asm volatile("cp.async.wait_group 0;" ::: "memory")

#define LDMX4(r0, r1, r2, r3, addr) \
    asm volatile("ldmatrix.sync.aligned.m8n8.x4.shared.b16 {%0,%1,%2,%3}, [%4];" \
                 : "=r"(r0), "=r"(r1), "=r"(r2), "=r"(r3) : "r"(addr))

__device__ __forceinline__ void mma16816(float* d, const uint32_t* a,
                                         uint32_t b0, uint32_t b1) {
    asm volatile("mma.sync.aligned.m16n8k16.row.col.f32.bf16.bf16.f32 "
                 "{%0,%1,%2,%3}, {%4,%5,%6,%7}, {%8,%9}, {%0,%1,%2,%3};"
                 : "+f"(d[0]), "+f"(d[1]), "+f"(d[2]), "+f"(d[3])
                 : "r"(a[0]), "r"(a[1]), "r"(a[2]), "r"(a[3]), "r"(b0), "r"(b1));
}

// ---------------- kernel 1: L2 normalize (blocks 0..2047) + W prep (blocks 2048..2111) ----------------
__global__ __launch_bounds__(256) void k_prep(const float* __restrict__ t,
                                              const float* __restrict__ d,
                                              const float* __restrict__ W1) {
    __shared__ float sh[32][65];
    const int tid = threadIdx.x;
    if (blockIdx.x < 2048) {
        int row = blockIdx.x;
        const float* src;
        float* dst;
        if (row < B_ * N_) { src = t + row * E_;            dst = g_tn + row * E_; }
        else               { int r = row - B_ * N_;
                             src = d + r * E_;              dst = g_dn + r * E_; }
        float x = src[tid];
        float s = x * x;
        #pragma unroll
        for (int o = 16; o > 0; o >>= 1) s += __shfl_xor_sync(0xffffffffu, s, o);
        if ((tid & 31) == 0) sh[0][tid >> 5] = s;
        __syncthreads();
        float tot = 0.f;
        #pragma unroll
        for (int i = 0; i < 8; i++) tot += sh[0][i];
        float inv = 1.f / fmaxf(sqrtf(tot), 1e-12f);
        dst[tid] = x * inv;
    } else {
        const int blk = blockIdx.x - 2048;
        const int c = blk & 7, hb = blk >> 3;
        {
            int kk0 = tid >> 6, hl = tid & 63;
            #pragma unroll
            for (int it = 0; it < 8; it++) {
                int k = kk0 + it * 4;
                sh[k][hl] = W1[(2 * E_ + c * 32 + k) * H_ + hb * 64 + hl];
            }
        }
        __syncthreads();
        const int hl = tid >> 2, jj = tid & 3;
        const int h = hb * 64 + hl;
        uint32_t hi[4], lo[4];
        #pragma unroll
        for (int i = 0; i < 4; i++) {
            float x0 = sh[jj * 8 + i * 2 + 0][hl];
            float x1 = sh[jj * 8 + i * 2 + 1][hl];
            __nv_bfloat16 h0 = __float2bfloat16(x0), h1 = __float2bfloat16(x1);
            __nv_bfloat16 l0 = __float2bfloat16(x0 - __bfloat162float(h0));
            __nv_bfloat16 l1 = __float2bfloat16(x1 - __bfloat162float(h1));
            hi[i] = pk2(h0, h1);
            lo[i] = pk2(l0, l1);
        }
        *(uint4*)(g_W + c * 65536 + SWZ(h * 128 + jj * 16))      = make_uint4(hi[0], hi[1], hi[2], hi[3]);
        *(uint4*)(g_W + c * 65536 + SWZ(h * 128 + 64 + jj * 16)) = make_uint4(lo[0], lo[1], lo[2], lo[3]);
    }
}

// ---------------- kernel 2: A = t@W1a + b1 ; Bv = d@W1b ----------------
__global__ __launch_bounds__(256) void k_ab(const float* __restrict__ W1,
                                            const float* __restrict__ b1) {
    const int z    = blockIdx.y;
    const int row0 = blockIdx.x * 16;
    const float* X = z ? g_dn : g_tn;
    float*       O = z ? g_Bv : g_A;
    const float* W = W1 + z * (E_ * H_);

    __shared__ float xs[16][17];
    __shared__ float wc[16][H_];

    const int tid = threadIdx.x, w = tid >> 5, l = tid & 31;
    float acc[2][16];
    #pragma unroll
    for (int r = 0; r < 2; r++)
        #pragma unroll
        for (int j = 0; j < 16; j++) acc[r][j] = 0.f;

    for (int c = 0; c < 16; c++) {
        __syncthreads();
        {
            int kk = tid >> 4, r = tid & 15;
            xs[kk][r] = X[(row0 + r) * E_ + c * 16 + kk];
        }
        {
            const float4* src = (const float4*)(W + c * 16 * H_);
            float4* dstp = (float4*)&wc[0][0];
            #pragma unroll
            for (int u = 0; u < 8; u++) dstp[tid + 256 * u] = src[tid + 256 * u];
        }
        __syncthreads();
        #pragma unroll 4
        for (int kk = 0; kk < 16; kk++) {
            float a0 = xs[kk][w * 2 + 0];
            float a1 = xs[kk][w * 2 + 1];
            #pragma unroll
            for (int j = 0; j < 16; j++) {
                float bv = wc[kk][l + 32 * j];
                acc[0][j] = fmaf(a0, bv, acc[0][j]);
                acc[1][j] = fmaf(a1, bv, acc[1][j]);
            }
        }
    }
    #pragma unroll
    for (int r = 0; r < 2; r++) {
        int row = row0 + w * 2 + r;
        #pragma unroll
        for (int j = 0; j < 16; j++) {
            int h = l + 32 * j;
            float v = acc[r][j] + (z == 0 ? b1[h] : 0.f);
            O[row * H_ + h] = v;
        }
    }
}

// ---------------- kernel 3: mma.sync bf16 3-pass GEMM + fused epilogue ----------------
enum {
    OFF_W    = 0,        // 2 x 64KB  W chunk double buffer
    OFF_A    = 131072,   // 2 x 8KB   |t-d| chunk double buffer
    OFF_TS   = 147456,   // 1KB  t row
    OFF_AS   = 148480,   // 2KB  A row
    OFF_GAM  = 150528,   // 2KB
    OFF_BET  = 152576,   // 2KB
    OFF_W2   = 154624,   // 2KB
    OFF_RED1 = 156672,   // 2KB  [8 hq][64 m]
    OFF_RED2 = 158720,   // 2KB
    SMEM_SZ  = 160768
};

__global__ void __launch_bounds__(512, 1) k_main(const float* __restrict__ gamma,
                                                 const float* __restrict__ beta,
                                                 const float* __restrict__ W2,
                                                 const float* __restrict__ b2,
                                                 float* __restrict__ out) {
    extern __shared__ __align__(16) char smem[];
    const uint32_t sbase = smem_u32(smem);
    const int tid = threadIdx.x, wid = tid >> 5, lid = tid & 31;
    const int b = blockIdx.z, n = blockIdx.y, m0 = blockIdx.x * 64;
    const int mw = wid >> 3, hq = wid & 7;

    float* ts   = (float*)(smem + OFF_TS);
    float* as_  = (float*)(smem + OFF_AS);
    float* gam  = (float*)(smem + OFF_GAM);
    float* bet  = (float*)(smem + OFF_BET);
    float* w2s  = (float*)(smem + OFF_W2);
    float* red1 = (float*)(smem + OFF_RED1);
    float* red2 = (float*)(smem + OFF_RED2);

    if (tid < 256) ts[tid] = g_tn[(b * N_ + n) * E_ + tid];
    {
        int h = tid;
        as_[h] = g_A[(b * N_ + n) * H_ + h];
        gam[h] = gamma[h];
        bet[h] = beta[h];
        w2s[h] = W2[h];
    }
    __syncthreads();

    // ---- chunk loaders ----
    const int am = tid >> 3, aj = tid & 7;   // A-build: m row (64), 4-k slice (8)
    const float* drowA = g_dn + (b * M_ + m0 + am) * E_;

    auto buildA = [&](int c, int buf) {
        const float4 dv = *(const float4*)(drowA + c * 32 + aj * 4);
        const float* tp = ts + c * 32 + aj * 4;
        float x0 = fabsf(tp[0] - dv.x), x1 = fabsf(tp[1] - dv.y);
        float x2 = fabsf(tp[2] - dv.z), x3 = fabsf(tp[3] - dv.w);
        __nv_bfloat16 h0 = __float2bfloat16(x0), h1 = __float2bfloat16(x1);
        __nv_bfloat16 h2 = __float2bfloat16(x2), h3 = __float2bfloat16(x3);
        __nv_bfloat16 l0 = __float2bfloat16(x0 - __bfloat162float(h0));
        __nv_bfloat16 l1 = __float2bfloat16(x1 - __bfloat162float(h1));
        __nv_bfloat16 l2 = __float2bfloat16(x2 - __bfloat162float(h2));
        __nv_bfloat16 l3 = __float2bfloat16(x3 - __bfloat162float(h3));
        char* abuf = smem + OFF_A + buf * 8192;
        *(uint2*)(abuf + SWZ(am * 128 + aj * 8))      = make_uint2(pk2(h0, h1), pk2(h2, h3));
        *(uint2*)(abuf + SWZ(am * 128 + 64 + aj * 8)) = make_uint2(pk2(l0, l1), pk2(l2, l3));
    };
    auto loadW = [&](int c, int buf) {
        const char* src = (const char*)g_W + c * 65536 + tid * 16;
        uint32_t dst = sbase + OFF_W + buf * 65536 + tid * 16;
        #pragma unroll
        for (int u = 0; u < 8; u++)
            CP_ASYNC16(dst + u * 8192, src + u * 8192);
    };

    // ---- accumulators + ldmatrix addressing ----
    float acc[2][8][4];
    #pragma unroll
    for (int mt = 0; mt < 2; mt++)
        #pragma unroll
        for (int nt = 0; nt < 8; nt++)
            #pragma unroll
            for (int r = 0; r < 4; r++) acc[mt][nt][r] = 0.f;

    const uint32_t arowoff = (uint32_t)(mw * 32 + (lid & 15)) * 128;
    const uint32_t asel    = (uint32_t)(lid >> 4) * 16;
    const uint32_t browoff = (uint32_t)(hq * 64 + (lid & 7) + ((lid >> 4) << 3)) * 128;
    const uint32_t bsel    = (uint32_t)((lid >> 3) & 1) * 16;
    const uint32_t xr      = (uint32_t)(lid & 7) << 4;

    auto gemm = [&](int buf) {
        const uint32_t aBase = sbase + OFF_A + buf * 8192  + arowoff;
        const uint32_t bBase = sbase + OFF_W + buf * 65536 + browoff;
        #pragma unroll
        for (int ks = 0; ks < 2; ks++) {
            const uint32_t ao_h = (ks * 32 + asel) ^ xr;
            const uint32_t ao_l = (64 + ks * 32 + asel) ^ xr;
            const uint32_t bo_h = (ks * 32 + bsel) ^ xr;
            const uint32_t bo_l = (64 + ks * 32 + bsel) ^ xr;
            uint32_t ah[2][4], al[2][4];
            #pragma unroll
            for (int mt = 0; mt < 2; mt++) {
                LDMX4(ah[mt][0], ah[mt][1], ah[mt][2], ah[mt][3], aBase + mt * 2048 + ao_h);
                LDMX4(al[mt][0], al[mt][1], al[mt][2], al[mt][3], aBase + mt * 2048 + ao_l);
            }
            #pragma unroll
            for (int ng = 0; ng < 2; ng++) {
                uint32_t bh[2][4], bl[2][4];
                #pragma unroll
                for (int np = 0; np < 2; np++) {
                    uint32_t bb = bBase + (ng * 2 + np) * 2048;
                    LDMX4(bh[np][0], bh[np][1], bh[np][2], bh[np][3], bb + bo_h);
                    LDMX4(bl[np][0], bl[np][1], bl[np][2], bl[np][3], bb + bo_l);
                }
                #pragma unroll
                for (int np = 0; np < 2; np++) {
                    const int nt = (ng * 2 + np) * 2;
                    #pragma unroll
                    for (int mt = 0; mt < 2; mt++) {
                        mma16816(acc[mt][nt + 0], ah[mt], bh[np][0], bh[np][1]);
                        mma16816(acc[mt][nt + 1], ah[mt], bh[np][2], bh[np][3]);
                        mma16816(acc[mt][nt + 0], ah[mt], bl[np][0], bl[np][1]);
                        mma16816(acc[mt][nt + 1], ah[mt], bl[np][2], bl[np][3]);
                        mma16816(acc[mt][nt + 0], al[mt], bh[np][0], bh[np][1]);
                        mma16816(acc[mt][nt + 1], al[mt], bh[np][2], bh[np][3]);
                    }
                }
            }
        }
    };

    // ---- pipelined K loop (8 chunks of 32) ----
    buildA(0, 0);
    loadW(0, 0);
    CP_COMMIT();
    CP_WAIT0();
    __syncthreads();
    #pragma unroll 2
    for (int c = 0; c < 8; c++) {
        const int buf = c & 1;
        if (c < 7) {
            loadW(c + 1, buf ^ 1);
            CP_COMMIT();
            buildA(c + 1, buf ^ 1);
        }
        gemm(buf);
        if (c < 7) CP_WAIT0();
        __syncthreads();
    }

    // ---- fused epilogue ----
    const float b2v = b2[0];
    float s1[2][2] = {{0.f, 0.f}, {0.f, 0.f}};
    float s2[2][2] = {{0.f, 0.f}, {0.f, 0.f}};
    const int mbase = m0 + mw * 32;
    #pragma unroll
    for (int mt = 0; mt < 2; mt++) {
        #pragma unroll
        for (int half = 0; half < 2; half++) {
            const int mr = mt * 16 + (lid >> 2) + half * 8;
            const float* bp = g_Bv + (b * M_ + mbase + mr) * H_ + hq * 64 + (lid & 3) * 2;
            #pragma unroll
            for (int nt = 0; nt < 8; nt++) {
                float2 bv = *(const float2*)(bp + nt * 8);
                int h = hq * 64 + nt * 8 + (lid & 3) * 2;
                float v0 = acc[mt][nt][half * 2 + 0] + as_[h + 0] + bv.x;
                float v1 = acc[mt][nt][half * 2 + 1] + as_[h + 1] + bv.y;
                acc[mt][nt][half * 2 + 0] = v0;
                acc[mt][nt][half * 2 + 1] = v1;
                s1[mt][half] += v0 + v1;
                s2[mt][half] = fmaf(v0, v0, fmaf(v1, v1, s2[mt][half]));
            }
        }
    }
    #pragma unroll
    for (int mt = 0; mt < 2; mt++)
        #pragma unroll
        for (int half = 0; half < 2; half++)
            #pragma unroll
            for (int o = 1; o <= 2; o <<= 1) {
                s1[mt][half] += __shfl_xor_sync(0xffffffffu, s1[mt][half], o);
                s2[mt][half] += __shfl_xor_sync(0xffffffffu, s2[mt][half], o);
            }
    if ((lid & 3) == 0) {
        #pragma unroll
        for (int mt = 0; mt < 2; mt++)
            #pragma unroll
            for (int half = 0; half < 2; half++) {
                int m = mw * 32 + mt * 16 + (lid >> 2) + half * 8;
                red1[hq * 64 + m] = s1[mt][half];
                red2[hq * 64 + m] = s2[mt][half];
            }
    }
    __syncthreads();
    float mu[2][2], inv[2][2];
    #pragma unroll
    for (int mt = 0; mt < 2; mt++)
        #pragma unroll
        for (int half = 0; half < 2; half++) {
            int m = mw * 32 + mt * 16 + (lid >> 2) + half * 8;
            float S1 = 0.f, S2 = 0.f;
            #pragma unroll
            for (int q = 0; q < 8; q++) {
                S1 += red1[q * 64 + m];
                S2 += red2[q * 64 + m];
            }
            float mm = S1 * (1.f / 512.f);
            mu[mt][half]  = mm;
            inv[mt][half] = rsqrtf(fmaxf(S2 * (1.f / 512.f) - mm * mm, 0.f) + 1e-5f);
        }
    __syncthreads();

    float o_[2][2] = {{0.f, 0.f}, {0.f, 0.f}};
    #pragma unroll
    for (int mt = 0; mt < 2; mt++) {
        #pragma unroll
        for (int half = 0; half < 2; half++) {
            float mm = mu[mt][half], iv = inv[mt][half];
            #pragma unroll
            for (int nt = 0; nt < 8; nt++) {
                int h = hq * 64 + nt * 8 + (lid & 3) * 2;
                #pragma unroll
                for (int e = 0; e < 2; e++) {
                    float v = acc[mt][nt][half * 2 + e];
                    float x = fmaf((v - mm) * iv, gam[h + e], bet[h + e]);
                    float sg = 1.f / (1.f + __expf(-x));
                    o_[mt][half] = fmaf(x * sg, w2s[h + e], o_[mt][half]);
                }
            }
        }
    }
    #pragma unroll
    for (int mt = 0; mt < 2; mt++)
        #pragma unroll
        for (int half = 0; half < 2; half++)
            #pragma unroll
            for (int o = 1; o <= 2; o <<= 1)
                o_[mt][half] += __shfl_xor_sync(0xffffffffu, o_[mt][half], o);
    if ((lid & 3) == 0) {
        #pragma unroll
        for (int mt = 0; mt < 2; mt++)
            #pragma unroll
            for (int half = 0; half < 2; half++) {
                int m = mw * 32 + mt * 16 + (lid >> 2) + half * 8;
                red1[hq * 64 + m] = o_[mt][half];
            }
    }
    __syncthreads();
    if (tid < 64) {
        int m = tid;
        float oo = b2v;
        #pragma unroll
        for (int q = 0; q < 8; q++) oo += red1[q * 64 + m];
        out[(b * N_ + n) * M_ + m0 + m] = oo;
    }
}

// ---------------- launch ----------------
extern "C" void kernel_launch(void* const* d_in, const int* in_sizes, int n_in,
                              void* d_out, int out_size) {
    const float* t     = (const float*)d_in[0];
    const float* d     = (const float*)d_in[1];
    const float* W1    = (const float*)d_in[2];
    const float* b1    = (const float*)d_in[3];
    const float* gamma = (const float*)d_in[4];
    const float* beta  = (const float*)d_in[5];
    const float* W2    = (const float*)d_in[6];
    const float* b2    = (const float*)d_in[7];
    float* out = (float*)d_out;

    cudaFuncSetAttribute(k_main, cudaFuncAttributeMaxDynamicSharedMemorySize, SMEM_SZ);

    k_prep<<<2048 + 64, 256>>>(t, d, W1);
    k_ab<<<dim3(64, 2), 256>>>(W1, b1);
    k_main<<<dim3(2, N_, B_), 512, SMEM_SZ>>>(gamma, beta, W2, b2, out);
}

// round 8
// speedup vs baseline: 2.3919x; 1.0011x over previous
#include <cuda_runtime.h>
#include <cuda_bf16.h>
#include <stdint.h>
#include <math.h>

#define B_ 8
#define N_ 128
#define M_ 128
#define E_ 256
#define H_ 512

// ---------------- scratch (no allocations allowed) ----------------
__device__ float g_tn[B_ * N_ * E_];   // l2-normalized track features
__device__ float g_dn[B_ * M_ * E_];   // l2-normalized det features
__device__ float g_A [B_ * N_ * H_];   // t_n @ W1[0:E]   + b1
__device__ float g_Bv[B_ * M_ * H_];   // d_m @ W1[E:2E]
// W1c^T split bf16: per 32-k chunk, 512 rows (h) x [hi 64B | lo 64B], swizzled
__device__ __align__(16) unsigned char g_W[8 * 65536];

// XOR bits[4:6] of the 128B row offset with (row & 7)
#define SWZ(o) ((o) ^ (((o) >> 3) & 0x70))

__device__ __forceinline__ uint32_t smem_u32(const void* p) {
    uint32_t a;
    asm("{ .reg .u64 t; cvta.to.shared.u64 t, %1; cvt.u32.u64 %0, t; }" : "=r"(a) : "l"(p));
    return a;
}
__device__ __forceinline__ uint32_t pk2(__nv_bfloat16 a, __nv_bfloat16 b) {
    return (uint32_t)__bfloat16_as_ushort(a) | ((uint32_t)__bfloat16_as_ushort(b) << 16);
}
#define CP_ASYNC16(dst, src) \
    asm volatile("cp.async.cg.shared.global [%0], [%1], 16;" :: "r"(dst), "l"(src) : "memory")
#define CP_COMMIT() asm volatile("cp.async.commit_group;" ::: "memory")
#define CP_WAIT0()  asm volatile("cp.async.wait_group 0;" ::: "memory")

#define LDMX4(r0, r1, r2, r3, addr) \
    asm volatile("ldmatrix.sync.aligned.m8n8.x4.shared.b16 {%0,%1,%2,%3}, [%4];" \
                 : "=r"(r0), "=r"(r1), "=r"(r2), "=r"(r3) : "r"(addr))

__device__ __forceinline__ void mma16816(float* d, const uint32_t* a,
                                         uint32_t b0, uint32_t b1) {
    asm volatile("mma.sync.aligned.m16n8k16.row.col.f32.bf16.bf16.f32 "
                 "{%0,%1,%2,%3}, {%4,%5,%6,%7}, {%8,%9}, {%0,%1,%2,%3};"
                 : "+f"(d[0]), "+f"(d[1]), "+f"(d[2]), "+f"(d[3])
                 : "r"(a[0]), "r"(a[1]), "r"(a[2]), "r"(a[3]), "r"(b0), "r"(b1));
}

// ---------------- kernel 1: L2 normalize (blocks 0..2047) + W prep (blocks 2048..2111) ----------------
__global__ __launch_bounds__(256) void k_prep(const float* __restrict__ t,
                                              const float* __restrict__ d,
                                              const float* __restrict__ W1) {
    __shared__ float sh[32][65];
    const int tid = threadIdx.x;
    if (blockIdx.x < 2048) {
        int row = blockIdx.x;
        const float* src;
        float* dst;
        if (row < B_ * N_) { src = t + row * E_;            dst = g_tn + row * E_; }
        else               { int r = row - B_ * N_;
                             src = d + r * E_;              dst = g_dn + r * E_; }
        float x = src[tid];
        float s = x * x;
        #pragma unroll
        for (int o = 16; o > 0; o >>= 1) s += __shfl_xor_sync(0xffffffffu, s, o);
        if ((tid & 31) == 0) sh[0][tid >> 5] = s;
        __syncthreads();
        float tot = 0.f;
        #pragma unroll
        for (int i = 0; i < 8; i++) tot += sh[0][i];
        float inv = 1.f / fmaxf(sqrtf(tot), 1e-12f);
        dst[tid] = x * inv;
    } else {
        const int blk = blockIdx.x - 2048;
        const int c = blk & 7, hb = blk >> 3;
        {
            int kk0 = tid >> 6, hl = tid & 63;
            #pragma unroll
            for (int it = 0; it < 8; it++) {
                int k = kk0 + it * 4;
                sh[k][hl] = W1[(2 * E_ + c * 32 + k) * H_ + hb * 64 + hl];
            }
        }
        __syncthreads();
        const int hl = tid >> 2, jj = tid & 3;
        const int h = hb * 64 + hl;
        uint32_t hi[4], lo[4];
        #pragma unroll
        for (int i = 0; i < 4; i++) {
            float x0 = sh[jj * 8 + i * 2 + 0][hl];
            float x1 = sh[jj * 8 + i * 2 + 1][hl];
            __nv_bfloat16 h0 = __float2bfloat16(x0), h1 = __float2bfloat16(x1);
            __nv_bfloat16 l0 = __float2bfloat16(x0 - __bfloat162float(h0));
            __nv_bfloat16 l1 = __float2bfloat16(x1 - __bfloat162float(h1));
            hi[i] = pk2(h0, h1);
            lo[i] = pk2(l0, l1);
        }
        *(uint4*)(g_W + c * 65536 + SWZ(h * 128 + jj * 16))      = make_uint4(hi[0], hi[1], hi[2], hi[3]);
        *(uint4*)(g_W + c * 65536 + SWZ(h * 128 + 64 + jj * 16)) = make_uint4(lo[0], lo[1], lo[2], lo[3]);
    }
}

// ---------------- kernel 2: A = t@W1a + b1 ; Bv = d@W1b ----------------
__global__ __launch_bounds__(256) void k_ab(const float* __restrict__ W1,
                                            const float* __restrict__ b1) {
    const int z    = blockIdx.y;
    const int row0 = blockIdx.x * 16;
    const float* X = z ? g_dn : g_tn;
    float*       O = z ? g_Bv : g_A;
    const float* W = W1 + z * (E_ * H_);

    __shared__ float xs[16][17];
    __shared__ float wc[16][H_];

    const int tid = threadIdx.x, w = tid >> 5, l = tid & 31;
    float acc[2][16];
    #pragma unroll
    for (int r = 0; r < 2; r++)
        #pragma unroll
        for (int j = 0; j < 16; j++) acc[r][j] = 0.f;

    for (int c = 0; c < 16; c++) {
        __syncthreads();
        {
            int kk = tid >> 4, r = tid & 15;
            xs[kk][r] = X[(row0 + r) * E_ + c * 16 + kk];
        }
        {
            const float4* src = (const float4*)(W + c * 16 * H_);
            float4* dstp = (float4*)&wc[0][0];
            #pragma unroll
            for (int u = 0; u < 8; u++) dstp[tid + 256 * u] = src[tid + 256 * u];
        }
        __syncthreads();
        #pragma unroll 4
        for (int kk = 0; kk < 16; kk++) {
            float a0 = xs[kk][w * 2 + 0];
            float a1 = xs[kk][w * 2 + 1];
            #pragma unroll
            for (int j = 0; j < 16; j++) {
                float bv = wc[kk][l + 32 * j];
                acc[0][j] = fmaf(a0, bv, acc[0][j]);
                acc[1][j] = fmaf(a1, bv, acc[1][j]);
            }
        }
    }
    #pragma unroll
    for (int r = 0; r < 2; r++) {
        int row = row0 + w * 2 + r;
        #pragma unroll
        for (int j = 0; j < 16; j++) {
            int h = l + 32 * j;
            float v = acc[r][j] + (z == 0 ? b1[h] : 0.f);
            O[row * H_ + h] = v;
        }
    }
}

// ---------------- kernel 3: mma.sync bf16 3-pass GEMM + fused epilogue ----------------
enum {
    OFF_W    = 0,        // 2 x 64KB  W chunk double buffer
    OFF_A    = 131072,   // 2 x 8KB   |t-d| chunk double buffer
    OFF_TS   = 147456,   // 1KB  t row
    OFF_AS   = 148480,   // 2KB  A row
    OFF_GAM  = 150528,   // 2KB
    OFF_BET  = 152576,   // 2KB
    OFF_W2   = 154624,   // 2KB
    OFF_RED1 = 156672,   // 2KB  [8 hq][64 m]
    OFF_RED2 = 158720,   // 2KB
    SMEM_SZ  = 160768
};

__global__ void __launch_bounds__(512, 1) k_main(const float* __restrict__ gamma,
                                                 const float* __restrict__ beta,
                                                 const float* __restrict__ W2,
                                                 const float* __restrict__ b2,
                                                 float* __restrict__ out) {
    extern __shared__ __align__(16) char smem[];
    const uint32_t sbase = smem_u32(smem);
    const int tid = threadIdx.x, wid = tid >> 5, lid = tid & 31;
    const int b = blockIdx.z, n = blockIdx.y, m0 = blockIdx.x * 64;
    const int mw = wid >> 3, hq = wid & 7;

    float* ts   = (float*)(smem + OFF_TS);
    float* as_  = (float*)(smem + OFF_AS);
    float* gam  = (float*)(smem + OFF_GAM);
    float* bet  = (float*)(smem + OFF_BET);
    float* w2s  = (float*)(smem + OFF_W2);
    float* red1 = (float*)(smem + OFF_RED1);
    float* red2 = (float*)(smem + OFF_RED2);

    if (tid < 256) ts[tid] = g_tn[(b * N_ + n) * E_ + tid];
    {
        int h = tid;
        as_[h] = g_A[(b * N_ + n) * H_ + h];
        gam[h] = gamma[h];
        bet[h] = beta[h];
        w2s[h] = W2[h];
    }
    __syncthreads();

    // ---- chunk loaders ----
    const int am = tid >> 3, aj = tid & 7;   // A-build: m row (64), 4-k slice (8)
    const float* drowA = g_dn + (b * M_ + m0 + am) * E_;

    auto buildA = [&](int c, int buf) {
        const float4 dv = *(const float4*)(drowA + c * 32 + aj * 4);
        const float* tp = ts + c * 32 + aj * 4;
        float x0 = fabsf(tp[0] - dv.x), x1 = fabsf(tp[1] - dv.y);
        float x2 = fabsf(tp[2] - dv.z), x3 = fabsf(tp[3] - dv.w);
        __nv_bfloat16 h0 = __float2bfloat16(x0), h1 = __float2bfloat16(x1);
        __nv_bfloat16 h2 = __float2bfloat16(x2), h3 = __float2bfloat16(x3);
        __nv_bfloat16 l0 = __float2bfloat16(x0 - __bfloat162float(h0));
        __nv_bfloat16 l1 = __float2bfloat16(x1 - __bfloat162float(h1));
        __nv_bfloat16 l2 = __float2bfloat16(x2 - __bfloat162float(h2));
        __nv_bfloat16 l3 = __float2bfloat16(x3 - __bfloat162float(h3));
        char* abuf = smem + OFF_A + buf * 8192;
        *(uint2*)(abuf + SWZ(am * 128 + aj * 8))      = make_uint2(pk2(h0, h1), pk2(h2, h3));
        *(uint2*)(abuf + SWZ(am * 128 + 64 + aj * 8)) = make_uint2(pk2(l0, l1), pk2(l2, l3));
    };
    auto loadW = [&](int c, int buf) {
        const char* src = (const char*)g_W + c * 65536 + tid * 16;
        uint32_t dst = sbase + OFF_W + buf * 65536 + tid * 16;
        #pragma unroll
        for (int u = 0; u < 8; u++)
            CP_ASYNC16(dst + u * 8192, src + u * 8192);
    };

    // ---- accumulators + ldmatrix addressing ----
    float acc[2][8][4];
    #pragma unroll
    for (int mt = 0; mt < 2; mt++)
        #pragma unroll
        for (int nt = 0; nt < 8; nt++)
            #pragma unroll
            for (int r = 0; r < 4; r++) acc[mt][nt][r] = 0.f;

    const uint32_t arowoff = (uint32_t)(mw * 32 + (lid & 15)) * 128;
    const uint32_t asel    = (uint32_t)(lid >> 4) * 16;
    const uint32_t browoff = (uint32_t)(hq * 64 + (lid & 7) + ((lid >> 4) << 3)) * 128;
    const uint32_t bsel    = (uint32_t)((lid >> 3) & 1) * 16;
    const uint32_t xr      = (uint32_t)(lid & 7) << 4;

    auto gemm = [&](int buf) {
        const uint32_t aBase = sbase + OFF_A + buf * 8192  + arowoff;
        const uint32_t bBase = sbase + OFF_W + buf * 65536 + browoff;
        #pragma unroll
        for (int ks = 0; ks < 2; ks++) {
            const uint32_t ao_h = (ks * 32 + asel) ^ xr;
            const uint32_t ao_l = (64 + ks * 32 + asel) ^ xr;
            const uint32_t bo_h = (ks * 32 + bsel) ^ xr;
            const uint32_t bo_l = (64 + ks * 32 + bsel) ^ xr;
            uint32_t ah[2][4], al[2][4];
            #pragma unroll
            for (int mt = 0; mt < 2; mt++) {
                LDMX4(ah[mt][0], ah[mt][1], ah[mt][2], ah[mt][3], aBase + mt * 2048 + ao_h);
                LDMX4(al[mt][0], al[mt][1], al[mt][2], al[mt][3], aBase + mt * 2048 + ao_l);
            }
            #pragma unroll
            for (int ng = 0; ng < 2; ng++) {
                uint32_t bh[2][4], bl[2][4];
                #pragma unroll
                for (int np = 0; np < 2; np++) {
                    uint32_t bb = bBase + (ng * 2 + np) * 2048;
                    LDMX4(bh[np][0], bh[np][1], bh[np][2], bh[np][3], bb + bo_h);
                    LDMX4(bl[np][0], bl[np][1], bl[np][2], bl[np][3], bb + bo_l);
                }
                #pragma unroll
                for (int np = 0; np < 2; np++) {
                    const int nt = (ng * 2 + np) * 2;
                    #pragma unroll
                    for (int mt = 0; mt < 2; mt++) {
                        mma16816(acc[mt][nt + 0], ah[mt], bh[np][0], bh[np][1]);
                        mma16816(acc[mt][nt + 1], ah[mt], bh[np][2], bh[np][3]);
                        mma16816(acc[mt][nt + 0], ah[mt], bl[np][0], bl[np][1]);
                        mma16816(acc[mt][nt + 1], ah[mt], bl[np][2], bl[np][3]);
                        mma16816(acc[mt][nt + 0], al[mt], bh[np][0], bh[np][1]);
                        mma16816(acc[mt][nt + 1], al[mt], bh[np][2], bh[np][3]);
                    }
                }
            }
        }
    };

    // ---- pipelined K loop (8 chunks of 32) ----
    buildA(0, 0);
    loadW(0, 0);
    CP_COMMIT();
    CP_WAIT0();
    __syncthreads();
    #pragma unroll 2
    for (int c = 0; c < 8; c++) {
        const int buf = c & 1;
        if (c < 7) {
            loadW(c + 1, buf ^ 1);
            CP_COMMIT();
            buildA(c + 1, buf ^ 1);
        }
        gemm(buf);
        if (c < 7) CP_WAIT0();
        __syncthreads();
    }

    // ---- fused epilogue ----
    const float b2v = b2[0];
    float s1[2][2] = {{0.f, 0.f}, {0.f, 0.f}};
    float s2[2][2] = {{0.f, 0.f}, {0.f, 0.f}};
    const int mbase = m0 + mw * 32;
    #pragma unroll
    for (int mt = 0; mt < 2; mt++) {
        #pragma unroll
        for (int half = 0; half < 2; half++) {
            const int mr = mt * 16 + (lid >> 2) + half * 8;
            const float* bp = g_Bv + (b * M_ + mbase + mr) * H_ + hq * 64 + (lid & 3) * 2;
            #pragma unroll
            for (int nt = 0; nt < 8; nt++) {
                float2 bv = *(const float2*)(bp + nt * 8);
                int h = hq * 64 + nt * 8 + (lid & 3) * 2;
                float v0 = acc[mt][nt][half * 2 + 0] + as_[h + 0] + bv.x;
                float v1 = acc[mt][nt][half * 2 + 1] + as_[h + 1] + bv.y;
                acc[mt][nt][half * 2 + 0] = v0;
                acc[mt][nt][half * 2 + 1] = v1;
                s1[mt][half] += v0 + v1;
                s2[mt][half] = fmaf(v0, v0, fmaf(v1, v1, s2[mt][half]));
            }
        }
    }
    #pragma unroll
    for (int mt = 0; mt < 2; mt++)
        #pragma unroll
        for (int half = 0; half < 2; half++)
            #pragma unroll
            for (int o = 1; o <= 2; o <<= 1) {
                s1[mt][half] += __shfl_xor_sync(0xffffffffu, s1[mt][half], o);
                s2[mt][half] += __shfl_xor_sync(0xffffffffu, s2[mt][half], o);
            }
    if ((lid & 3) == 0) {
        #pragma unroll
        for (int mt = 0; mt < 2; mt++)
            #pragma unroll
            for (int half = 0; half < 2; half++) {
                int m = mw * 32 + mt * 16 + (lid >> 2) + half * 8;
                red1[hq * 64 + m] = s1[mt][half];
                red2[hq * 64 + m] = s2[mt][half];
            }
    }
    __syncthreads();
    float mu[2][2], inv[2][2];
    #pragma unroll
    for (int mt = 0; mt < 2; mt++)
        #pragma unroll
        for (int half = 0; half < 2; half++) {
            int m = mw * 32 + mt * 16 + (lid >> 2) + half * 8;
            float S1 = 0.f, S2 = 0.f;
            #pragma unroll
            for (int q = 0; q < 8; q++) {
                S1 += red1[q * 64 + m];
                S2 += red2[q * 64 + m];
            }
            float mm = S1 * (1.f / 512.f);
            mu[mt][half]  = mm;
            inv[mt][half] = rsqrtf(fmaxf(S2 * (1.f / 512.f) - mm * mm, 0.f) + 1e-5f);
        }
    __syncthreads();

    float o_[2][2] = {{0.f, 0.f}, {0.f, 0.f}};
    #pragma unroll
    for (int mt = 0; mt < 2; mt++) {
        #pragma unroll
        for (int half = 0; half < 2; half++) {
            float mm = mu[mt][half], iv = inv[mt][half];
            #pragma unroll
            for (int nt = 0; nt < 8; nt++) {
                int h = hq * 64 + nt * 8 + (lid & 3) * 2;
                #pragma unroll
                for (int e = 0; e < 2; e++) {
                    float v = acc[mt][nt][half * 2 + e];
                    float x = fmaf((v - mm) * iv, gam[h + e], bet[h + e]);
                    float sg = 1.f / (1.f + __expf(-x));
                    o_[mt][half] = fmaf(x * sg, w2s[h + e], o_[mt][half]);
                }
            }
        }
    }
    #pragma unroll
    for (int mt = 0; mt < 2; mt++)
        #pragma unroll
        for (int half = 0; half < 2; half++)
            #pragma unroll
            for (int o = 1; o <= 2; o <<= 1)
                o_[mt][half] += __shfl_xor_sync(0xffffffffu, o_[mt][half], o);
    if ((lid & 3) == 0) {
        #pragma unroll
        for (int mt = 0; mt < 2; mt++)
            #pragma unroll
            for (int half = 0; half < 2; half++) {
                int m = mw * 32 + mt * 16 + (lid >> 2) + half * 8;
                red1[hq * 64 + m] = o_[mt][half];
            }
    }
    __syncthreads();
    if (tid < 64) {
        int m = tid;
        float oo = b2v;
        #pragma unroll
        for (int q = 0; q < 8; q++) oo += red1[q * 64 + m];
        out[(b * N_ + n) * M_ + m0 + m] = oo;
    }
}

// ---------------- launch ----------------
extern "C" void kernel_launch(void* const* d_in, const int* in_sizes, int n_in,
                              void* d_out, int out_size) {
    const float* t     = (const float*)d_in[0];
    const float* d     = (const float*)d_in[1];
    const float* W1    = (const float*)d_in[2];
    const float* b1    = (const float*)d_in[3];
    const float* gamma = (const float*)d_in[4];
    const float* beta  = (const float*)d_in[5];
    const float* W2    = (const float*)d_in[6];
    const float* b2    = (const float*)d_in[7];
    float* out = (float*)d_out;

    cudaFuncSetAttribute(k_main, cudaFuncAttributeMaxDynamicSharedMemorySize, SMEM_SZ);

    k_prep<<<2048 + 64, 256>>>(t, d, W1);
    k_ab<<<dim3(64, 2), 256>>>(W1, b1);
    k_main<<<dim3(2, N_, B_), 512, SMEM_SZ>>>(gamma, beta, W2, b2, out);
}